// round 13
// baseline (speedup 1.0000x reference)
#include <cuda_runtime.h>
#include <cuda_fp16.h>
#include <math.h>
#include <stdint.h>

#define Bb 16
#define Cc 384
#define Nn 4096
#define HEADS 8
#define CH 48
#define SSZ (Bb*Cc*Cc)
#define WSZ (Cc*Cc)
#define KT 6

// ---------------- scratch (device globals; allocation-free) ----------------
__device__ __half g_Sh[SSZ];                // S fp16
__device__ __half g_Mh[SSZ];                // folded (A+I)W3 + I (fp16)
__device__ __half g_Xh[(size_t)Bb*Cc*Nn];   // x fp16 [b][c][n]
__device__ __half g_W1h[WSZ], g_W2h[WSZ];   // weights fp16
__device__ float g_U1[SSZ], g_U2[SSZ];
__device__ float g_sx[Bb*Cc];               // row sums
__device__ float g_mb[Bb*Cc];
__device__ float g_Gp[KT*Bb*HEADS*CH*CH];   // split-K partial Gqk
__device__ float g_rp[KT*Bb*HEADS*4*CH];    // split-K partial row reductions

// ---------------- PTX helpers (sm_80-class; no 'a'-gated features) ---------
__device__ __forceinline__ uint32_t smem_u32(const void* p) {
    uint32_t a;
    asm("{ .reg .u64 t; cvta.to.shared.u64 t, %1; cvt.u32.u64 %0, t; }"
        : "=r"(a) : "l"(p));
    return a;
}
__device__ __forceinline__ void ldsm4(uint32_t* r, uint32_t addr) {
    asm volatile("ldmatrix.sync.aligned.m8n8.x4.shared.b16 {%0,%1,%2,%3}, [%4];"
                 : "=r"(r[0]), "=r"(r[1]), "=r"(r[2]), "=r"(r[3]) : "r"(addr));
}
__device__ __forceinline__ void ldsm4t(uint32_t* r, uint32_t addr) {
    asm volatile("ldmatrix.sync.aligned.m8n8.x4.trans.shared.b16 {%0,%1,%2,%3}, [%4];"
                 : "=r"(r[0]), "=r"(r[1]), "=r"(r[2]), "=r"(r[3]) : "r"(addr));
}
__device__ __forceinline__ void mma16816(float* c, const uint32_t* a, const uint32_t* b) {
    asm volatile(
        "mma.sync.aligned.m16n8k16.row.col.f32.f16.f16.f32 "
        "{%0,%1,%2,%3}, {%4,%5,%6,%7}, {%8,%9}, {%0,%1,%2,%3};"
        : "+f"(c[0]), "+f"(c[1]), "+f"(c[2]), "+f"(c[3])
        : "r"(a[0]), "r"(a[1]), "r"(a[2]), "r"(a[3]), "r"(b[0]), "r"(b[1]));
}
#define CP_ASYNC16(dst, src) \
    asm volatile("cp.async.cg.shared.global [%0], [%1], 16;" \
                 :: "r"(dst), "l"(__cvta_generic_to_global(src)))
#define CP_COMMIT() asm volatile("cp.async.commit_group;" ::: "memory")
#define CP_WAIT0()  asm volatile("cp.async.wait_group 0;" ::: "memory")
#define CP_WAIT1()  asm volatile("cp.async.wait_group 1;" ::: "memory")

// smem geometry
#define SROW80    80
#define ATILE     10240
#define STAGE_S1  20480     // Ah, Bh (1-pass NT); 3 stages
#define DSMEM_S   69632
#define AROW144   144
#define ATILE_O   18432
#define BPITCH    272
#define STAGE_O   35840     // 2 stages
#define DSMEM_O   71680
#define ATTN1_SM  25344     // 2 * 48 * 66 * 4

// ---------------------------------------------------------------------------
// compute bodies (warp tile 32x64; acc[2][8][4])
// ---------------------------------------------------------------------------
__device__ __forceinline__ void compute_nt1(uint32_t smb, int wm, int wn, int lane,
                                            float acc[2][8][4]) {
    const int grp = lane >> 3, lr = lane & 7;
#pragma unroll
    for (int ks = 0; ks < 2; ks++) {
        const int kc = ks * 16;
        uint32_t ah[2][4];
#pragma unroll
        for (int ti = 0; ti < 2; ti++) {
            int row = wm * 32 + ti * 16 + lr + (grp & 1) * 8;
            int col = kc + (grp >> 1) * 8;
            ldsm4(ah[ti], smb + row * SROW80 + col * 2);
        }
#pragma unroll
        for (int half = 0; half < 2; half++) {
            uint32_t bhf[4][2];
#pragma unroll
            for (int p = 0; p < 2; p++) {
                int nrow = wn * 64 + half * 32 + p * 16 + (grp >> 1) * 8 + lr;
                int col = kc + (grp & 1) * 8;
                uint32_t r4[4];
                ldsm4(r4, smb + ATILE + nrow * SROW80 + col * 2);
                bhf[2*p][0] = r4[0]; bhf[2*p][1] = r4[1];
                bhf[2*p+1][0] = r4[2]; bhf[2*p+1][1] = r4[3];
            }
#pragma unroll
            for (int ti = 0; ti < 2; ti++)
#pragma unroll
                for (int tj = 0; tj < 4; tj++)
                    mma16816(acc[ti][half * 4 + tj], ah[ti], bhf[tj]);
        }
    }
}

__device__ __forceinline__ void compute_o(uint32_t smbA, uint32_t smbB,
                                          int wm, int wn, int lane,
                                          float acc[2][8][4]) {
    const int grp = lane >> 3, lr = lane & 7;
#pragma unroll
    for (int ks = 0; ks < 4; ks++) {
        const int kc = ks * 16;
        uint32_t ah[2][4];
#pragma unroll
        for (int ti = 0; ti < 2; ti++) {
            int row = wm * 32 + ti * 16 + lr + (grp & 1) * 8;
            int col = kc + (grp >> 1) * 8;
            ldsm4(ah[ti], smbA + row * AROW144 + col * 2);
        }
#pragma unroll
        for (int half = 0; half < 2; half++) {
            uint32_t bhf[4][2];
#pragma unroll
            for (int p = 0; p < 2; p++) {
                int krow = kc + ((lane >> 3) & 1) * 8 + (lane & 7);
                int ncol = wn * 64 + half * 32 + p * 16 + (lane >> 4) * 8;
                uint32_t r4[4];
                ldsm4t(r4, smbB + krow * BPITCH + ncol * 2);
                bhf[2*p][0] = r4[0]; bhf[2*p][1] = r4[1];
                bhf[2*p+1][0] = r4[2]; bhf[2*p+1][1] = r4[3];
            }
#pragma unroll
            for (int ti = 0; ti < 2; ti++)
#pragma unroll
                for (int tj = 0; tj < 4; tj++)
                    mma16816(acc[ti][half * 4 + tj], ah[ti], bhf[tj]);
        }
    }
}

// ---------------------------------------------------------------------------
// k_convert: x -> g_Xh (fp16) + g_sx (row sums). grid (Bb*Cc), 256 thr.
// ---------------------------------------------------------------------------
__global__ void __launch_bounds__(256) k_convert(const float* __restrict__ x) {
    const int row = blockIdx.x;
    const float4* xr = (const float4*)(x + (size_t)row * Nn);
    __half* xo = g_Xh + (size_t)row * Nn;
    float s = 0.f;
#pragma unroll
    for (int j = 0; j < 4; j++) {
        int idx = threadIdx.x + 256 * j;
        float4 v = xr[idx];
        s += (v.x + v.y) + (v.z + v.w);
        __half2 h01 = __floats2half2_rn(v.x, v.y);
        __half2 h23 = __floats2half2_rn(v.z, v.w);
        uint2 hh;
        hh.x = *(uint32_t*)&h01; hh.y = *(uint32_t*)&h23;
        *(uint2*)(xo + idx * 4) = hh;
    }
    __shared__ float red[256];
    red[threadIdx.x] = s;
    __syncthreads();
    for (int o = 128; o; o >>= 1) {
        if (threadIdx.x < o) red[threadIdx.x] += red[threadIdx.x + o];
        __syncthreads();
    }
    if (threadIdx.x == 0) g_sx[row] = red[0];
}

// k_convW: w1,w2 -> fp16. grid (WSZ/1024, 2), 256 thr.
__global__ void __launch_bounds__(256) k_convW(const float* __restrict__ w1,
                                               const float* __restrict__ w2) {
    const float* src = blockIdx.y ? w2 : w1;
    __half* dst = blockIdx.y ? g_W2h : g_W1h;
    int base = blockIdx.x * 1024 + threadIdx.x * 4;
    float4 v = *(const float4*)(src + base);
    __half2 h01 = __floats2half2_rn(v.x, v.y);
    __half2 h23 = __floats2half2_rn(v.z, v.w);
    uint2 hh;
    hh.x = *(uint32_t*)&h01; hh.y = *(uint32_t*)&h23;
    *(uint2*)(dst + base) = hh;
}

// ---------------------------------------------------------------------------
// S GEMM, triangle, full-K, 1-pass, cp.async 3-stage, fp16 in.
// Writes Sh tile + (off-diag) transpose directly. grid (6 pairs, 16 batch)
// ---------------------------------------------------------------------------
__global__ void __launch_bounds__(256) gemm_S() {
    extern __shared__ char dsm[];
    const int pxl[6] = {0,0,0,1,1,2}, pyl[6] = {0,1,2,1,2,2};
    const int tid = threadIdx.x, lane = tid & 31, wid = tid >> 5;
    const int wm = wid & 3, wn = wid >> 2;
    const int pair = blockIdx.x, bz = blockIdx.y;
    const int bx = pxl[pair], by = pyl[pair];
    const uint32_t smb = smem_u32(dsm);

    const __half* Ax = g_Xh + ((size_t)bz * Cc + bx * 128) * Nn;
    const __half* Bx = g_Xh + ((size_t)bz * Cc + by * 128) * Nn;

    int rw[2], qq[2];
#pragma unroll
    for (int j = 0; j < 2; j++) { int u = tid + 256 * j; rw[j] = u >> 2; qq[j] = u & 3; }

    float acc[2][8][4];
#pragma unroll
    for (int i = 0; i < 2; i++)
#pragma unroll
        for (int j = 0; j < 8; j++)
#pragma unroll
            for (int q = 0; q < 4; q++) acc[i][j][q] = 0.f;

#define ISSUE_S(chunk, stage) do { \
    uint32_t _b = smb + (stage) * STAGE_S1; \
    int _k = (chunk) * 32; \
    _Pragma("unroll") \
    for (int _j = 0; _j < 2; _j++) { \
        CP_ASYNC16(_b + rw[_j] * SROW80 + qq[_j] * 16, \
                   Ax + (size_t)rw[_j] * Nn + _k + qq[_j] * 8); \
        CP_ASYNC16(_b + ATILE + rw[_j] * SROW80 + qq[_j] * 16, \
                   Bx + (size_t)rw[_j] * Nn + _k + qq[_j] * 8); \
    } } while (0)

    ISSUE_S(0, 0); CP_COMMIT();
    ISSUE_S(1, 1); CP_COMMIT();

    const int nch = Nn / 32;   // 128
    int st = 0;
    for (int i = 0; i < nch; i++) {
        if (i == nch - 1) CP_WAIT0(); else CP_WAIT1();
        __syncthreads();
        if (i + 2 < nch) {
            int s2 = st + 2; if (s2 >= 3) s2 -= 3;
            ISSUE_S(i + 2, s2); CP_COMMIT();
        }
        compute_nt1(smb + st * STAGE_S1, wm, wn, lane, acc);
        if (++st == 3) st = 0;
    }
    __syncthreads();
#undef ISSUE_S

    float* sC = (float*)dsm;
#pragma unroll
    for (int ti = 0; ti < 2; ti++)
#pragma unroll
        for (int j = 0; j < 8; j++) {
            int row0 = wm * 32 + ti * 16 + (lane >> 2);
            int col  = wn * 64 + j * 8 + (lane & 3) * 2;
            *(float2*)(sC + row0 * 132 + col)       = make_float2(acc[ti][j][0], acc[ti][j][1]);
            *(float2*)(sC + (row0 + 8) * 132 + col) = make_float2(acc[ti][j][2], acc[ti][j][3]);
        }
    __syncthreads();

    const size_t gb = (size_t)bz * Cc * Cc;
    const int r0 = tid >> 1, half = tid & 1;

    // direct tile write (fp16, coalesced)
    {
        const float* src = sC + r0 * 132 + half * 64;
        __half* dst = g_Sh + gb + (size_t)(bx * 128 + r0) * Cc + by * 128 + half * 64;
#pragma unroll
        for (int g = 0; g < 8; g++) {
            uint4 v;
            __half2 p0 = __floats2half2_rn(src[g*8+0], src[g*8+1]);
            __half2 p1 = __floats2half2_rn(src[g*8+2], src[g*8+3]);
            __half2 p2 = __floats2half2_rn(src[g*8+4], src[g*8+5]);
            __half2 p3 = __floats2half2_rn(src[g*8+6], src[g*8+7]);
            v.x = *(uint32_t*)&p0; v.y = *(uint32_t*)&p1;
            v.z = *(uint32_t*)&p2; v.w = *(uint32_t*)&p3;
            *(uint4*)(dst + g * 8) = v;
        }
    }
    // transposed write (off-diagonal pairs)
    if (bx != by) {
        const int c = r0;   // column of original tile
        __half* dstT = g_Sh + gb + (size_t)(by * 128 + c) * Cc + bx * 128 + half * 64;
#pragma unroll
        for (int g = 0; g < 8; g++) {
            uint4 v;
            const float* s0 = sC + (half * 64 + g * 8) * 132 + c;
            __half2 p0 = __floats2half2_rn(s0[0*132], s0[1*132]);
            __half2 p1 = __floats2half2_rn(s0[2*132], s0[3*132]);
            __half2 p2 = __floats2half2_rn(s0[4*132], s0[5*132]);
            __half2 p3 = __floats2half2_rn(s0[6*132], s0[7*132]);
            v.x = *(uint32_t*)&p0; v.y = *(uint32_t*)&p1;
            v.z = *(uint32_t*)&p2; v.w = *(uint32_t*)&p3;
            *(uint4*)(dstT + g * 8) = v;
        }
    }
}

// ---------------------------------------------------------------------------
// U GEMM (fused U1+U2), 1-pass, cp.async 3-stage, fp16 W. grid (6,3,16).
// ---------------------------------------------------------------------------
__global__ void __launch_bounds__(256) gemm_U() {
    extern __shared__ char dsm[];
    const int tid = threadIdx.x, lane = tid & 31, wid = tid >> 5;
    const int wm = wid & 3, wn = wid >> 2;
    const int sel = blockIdx.x >= 3;
    const int bx = blockIdx.x - (sel ? 3 : 0);
    const int by = blockIdx.y, bz = blockIdx.z;
    const uint32_t smb = smem_u32(dsm);

    const __half* Ax = (sel ? g_W2h : g_W1h) + (size_t)bx * 128 * Cc;
    const __half* Bx = g_Sh + (size_t)bz * Cc * Cc + (size_t)by * 128 * Cc;
    float* Cf = sel ? g_U2 : g_U1;

    int rw[2], qq[2];
#pragma unroll
    for (int j = 0; j < 2; j++) { int u = tid + 256 * j; rw[j] = u >> 2; qq[j] = u & 3; }

    float acc[2][8][4];
#pragma unroll
    for (int i = 0; i < 2; i++)
#pragma unroll
        for (int j = 0; j < 8; j++)
#pragma unroll
            for (int q = 0; q < 4; q++) acc[i][j][q] = 0.f;

#define ISSUE_U(chunk, stage) do { \
    uint32_t _b = smb + (stage) * STAGE_S1; \
    int _k = (chunk) * 32; \
    _Pragma("unroll") \
    for (int _j = 0; _j < 2; _j++) { \
        CP_ASYNC16(_b + rw[_j] * SROW80 + qq[_j] * 16, \
                   Ax + (size_t)rw[_j] * Cc + _k + qq[_j] * 8); \
        CP_ASYNC16(_b + ATILE + rw[_j] * SROW80 + qq[_j] * 16, \
                   Bx + (size_t)rw[_j] * Cc + _k + qq[_j] * 8); \
    } } while (0)

    ISSUE_U(0, 0); CP_COMMIT();
    ISSUE_U(1, 1); CP_COMMIT();

    const int nch = Cc / 32;   // 12
    int st = 0;
    for (int i = 0; i < nch; i++) {
        if (i == nch - 1) CP_WAIT0(); else CP_WAIT1();
        __syncthreads();
        if (i + 2 < nch) {
            int s2 = st + 2; if (s2 >= 3) s2 -= 3;
            ISSUE_U(i + 2, s2); CP_COMMIT();
        }
        compute_nt1(smb + st * STAGE_S1, wm, wn, lane, acc);
        if (++st == 3) st = 0;
    }
    __syncthreads();
#undef ISSUE_U

    float* sC = (float*)dsm;
#pragma unroll
    for (int ti = 0; ti < 2; ti++)
#pragma unroll
        for (int j = 0; j < 8; j++) {
            int row0 = wm * 32 + ti * 16 + (lane >> 2);
            int col  = wn * 64 + j * 8 + (lane & 3) * 2;
            *(float2*)(sC + row0 * 132 + col)       = make_float2(acc[ti][j][0], acc[ti][j][1]);
            *(float2*)(sC + (row0 + 8) * 132 + col) = make_float2(acc[ti][j][2], acc[ti][j][3]);
        }
    __syncthreads();

    const int r0 = tid >> 1, half = tid & 1;
    const float* src = sC + r0 * 132 + half * 64;
    size_t base = ((size_t)bz * Cc + bx * 128 + r0) * Cc + by * 128 + half * 64;
#pragma unroll
    for (int j = 0; j < 64; j += 4)
        *(float4*)(Cf + base + j) = *(const float4*)(src + j);
}

// ---------------------------------------------------------------------------
// out GEMM, 1-pass, BK=64, cp.async 2-stage: out = Mh Xh + mb. grid (3,32,16).
// ---------------------------------------------------------------------------
__global__ void __launch_bounds__(256) gemm_out(float* __restrict__ out)
{
    extern __shared__ char dsm[];
    const int tid = threadIdx.x, lane = tid & 31, wid = tid >> 5;
    const int wm = wid & 3, wn = wid >> 2;
    const int bx = blockIdx.x, by = blockIdx.y, bz = blockIdx.z;
    const uint32_t smb = smem_u32(dsm);

    const __half* pA = g_Mh + (size_t)bz * Cc * Cc + (size_t)bx * 128 * Cc;
    const __half* pB = g_Xh + (size_t)bz * Cc * Nn + by * 128;

    int arw[4], aq[4];
#pragma unroll
    for (int j = 0; j < 4; j++) { int u = tid + 256 * j; arw[j] = u >> 3; aq[j] = u & 7; }
    int brw[4], bq[4];
#pragma unroll
    for (int j = 0; j < 4; j++) { int u = tid + 256 * j; brw[j] = u >> 4; bq[j] = u & 15; }

    float acc[2][8][4];
#pragma unroll
    for (int i = 0; i < 2; i++)
#pragma unroll
        for (int j = 0; j < 8; j++)
#pragma unroll
            for (int q = 0; q < 4; q++) acc[i][j][q] = 0.f;

#define ISSUE_O(chunk, stage) do { \
    uint32_t _b = smb + (stage) * STAGE_O; \
    int _k = (chunk) * 64; \
    _Pragma("unroll") \
    for (int _j = 0; _j < 4; _j++) { \
        CP_ASYNC16(_b + arw[_j] * AROW144 + aq[_j] * 16, \
                   pA + (size_t)arw[_j] * Cc + _k + aq[_j] * 8); \
        CP_ASYNC16(_b + ATILE_O + brw[_j] * BPITCH + bq[_j] * 16, \
                   pB + (size_t)(_k + brw[_j]) * Nn + bq[_j] * 8); \
    } } while (0)

    ISSUE_O(0, 0); CP_COMMIT();

    const int nch = Cc / 64;   // 6
    for (int i = 0; i < nch; i++) {
        CP_WAIT0();
        __syncthreads();
        if (i + 1 < nch) { ISSUE_O(i + 1, (i + 1) & 1); CP_COMMIT(); }
        uint32_t st = smb + (i & 1) * STAGE_O;
        compute_o(st, st + ATILE_O, wm, wn, lane, acc);
    }
    __syncthreads();
#undef ISSUE_O

    float* sC = (float*)dsm;
#pragma unroll
    for (int ti = 0; ti < 2; ti++)
#pragma unroll
        for (int j = 0; j < 8; j++) {
            int row0 = wm * 32 + ti * 16 + (lane >> 2);
            int col  = wn * 64 + j * 8 + (lane & 3) * 2;
            *(float2*)(sC + row0 * 132 + col)       = make_float2(acc[ti][j][0], acc[ti][j][1]);
            *(float2*)(sC + (row0 + 8) * 132 + col) = make_float2(acc[ti][j][2], acc[ti][j][3]);
        }
    __syncthreads();

    const int r0 = tid >> 1, half = tid & 1;
    const float* src = sC + r0 * 132 + half * 64;
    const int grow = bx * 128 + r0;
    float bias = g_mb[bz * Cc + grow];
    size_t base = ((size_t)bz * Cc + grow) * (size_t)Nn + by * 128 + half * 64;
#pragma unroll
    for (int j = 0; j < 64; j += 4) {
        float4 v4 = *(const float4*)(src + j);
        *(float4*)(out + base + j) = make_float4(v4.x + bias, v4.y + bias,
                                                 v4.z + bias, v4.w + bias);
    }
}

// ---------------------------------------------------------------------------
// k_attn1: split-K (6 x 64-wide) partial Gqk + row reductions.
// grid (KT, HEADS, Bb).
// ---------------------------------------------------------------------------
__global__ void __launch_bounds__(256) k_attn1(
    const float* __restrict__ w1, const float* __restrict__ w2)
{
    extern __shared__ float satt[];       // sU[48*66], sW[48*66]
    float* sU = satt;
    float* sW = satt + CH * 66;

    const int kt = blockIdx.x, h = blockIdx.y, b = blockIdx.z;
    const int k0 = kt * 64;
    const int tid = threadIdx.x;
    const int warp = tid >> 5, lane = tid & 31;

    const float* U1  = &g_U1[(size_t)b * Cc * Cc + (size_t)h * CH * Cc];
    const float* U2  = &g_U2[(size_t)b * Cc * Cc + (size_t)h * CH * Cc];
    const float* w1h = w1 + (size_t)h * CH * Cc;
    const float* w2h = w2 + (size_t)h * CH * Cc;

    for (int i = tid; i < CH * 64; i += 256) {
        int c = i >> 6, kk = i & 63;
        sU[c * 66 + kk] = U1[c * Cc + k0 + kk];
        sW[c * 66 + kk] = w2h[c * Cc + k0 + kk];
    }
    __syncthreads();

    const int ci0 = (tid >> 4) * 3, di0 = (tid & 15) * 3;
    float acc[3][3];
#pragma unroll
    for (int i = 0; i < 3; i++)
#pragma unroll
        for (int j = 0; j < 3; j++) acc[i][j] = 0.f;
#pragma unroll 8
    for (int kk = 0; kk < 64; kk++) {
        float u[3], w[3];
#pragma unroll
        for (int i = 0; i < 3; i++) u[i] = sU[(ci0 + i) * 66 + kk];
#pragma unroll
        for (int j = 0; j < 3; j++) w[j] = sW[(di0 + j) * 66 + kk];
#pragma unroll
        for (int i = 0; i < 3; i++)
#pragma unroll
            for (int j = 0; j < 3; j++) acc[i][j] += u[i] * w[j];
    }
    float* Gp = g_Gp + (((size_t)kt * Bb + b) * HEADS + h) * (CH * CH);
#pragma unroll
    for (int i = 0; i < 3; i++)
#pragma unroll
        for (int j = 0; j < 3; j++)
            Gp[(ci0 + i) * CH + di0 + j] = acc[i][j];

    float* rp = g_rp + (((size_t)kt * Bb + b) * HEADS + h) * (4 * CH);
    for (int c = warp * 6; c < warp * 6 + 6; c++) {
        float aq = 0.f, ak = 0.f, p1 = 0.f, p2 = 0.f;
#pragma unroll
        for (int it = 0; it < 2; it++) {
            int k = k0 + lane + it * 32;
            float w1v = w1h[c * Cc + k];
            float w2v = w2h[c * Cc + k];
            aq += U1[c * Cc + k] * w1v;
            ak += U2[c * Cc + k] * w2v;
            float sv = g_sx[(size_t)b * Cc + k];
            p1 += w1v * sv;
            p2 += w2v * sv;
        }
#pragma unroll
        for (int o = 16; o; o >>= 1) {
            aq += __shfl_xor_sync(0xffffffffu, aq, o);
            ak += __shfl_xor_sync(0xffffffffu, ak, o);
            p1 += __shfl_xor_sync(0xffffffffu, p1, o);
            p2 += __shfl_xor_sync(0xffffffffu, p2, o);
        }
        if (lane == 0) {
            rp[0 * CH + c] = aq;
            rp[1 * CH + c] = ak;
            rp[2 * CH + c] = p1;
            rp[3 * CH + c] = p2;
        }
    }
}

// ---------------------------------------------------------------------------
// k_foldM: combine partials -> softmax A (redundant per kt), fold M k-slice,
// kt==0 writes mb. grid (3, HEADS, Bb).
// ---------------------------------------------------------------------------
__global__ void __launch_bounds__(256) k_foldM(
    const float* __restrict__ w3, const float* __restrict__ b1,
    const float* __restrict__ b2, const float* __restrict__ b3,
    const float* __restrict__ temp)
{
    __shared__ float sAa[CH * 49];
    __shared__ float sW[CH * 130];
    __shared__ float sNq[CH], sNk[CH], sP1[CH], sP2[CH];
    __shared__ float sB1[CH], sB2[CH], sB3[CH];

    const int kt = blockIdx.x, h = blockIdx.y, b = blockIdx.z;
    const int k0 = kt * 128;
    const int tid = threadIdx.x;
    const int warp = tid >> 5, lane = tid & 31;

    const size_t gstr = (size_t)Bb * HEADS * CH * CH;
    const size_t rstr = (size_t)Bb * HEADS * 4 * CH;
    const float* Gp = g_Gp + ((size_t)b * HEADS + h) * (CH * CH);
    const float* rp = g_rp + ((size_t)b * HEADS + h) * (4 * CH);
    const float* w3h = w3 + (size_t)h * CH * Cc;

    if (tid < CH) {
        sB1[tid] = b1[h * CH + tid];
        sB2[tid] = b2[h * CH + tid];
        sB3[tid] = b3[h * CH + tid];
        float nq = 0.f, nk = 0.f, p1 = 0.f, p2 = 0.f;
#pragma unroll
        for (int t = 0; t < KT; t++) {
            nq += rp[t * rstr + 0 * CH + tid];
            nk += rp[t * rstr + 1 * CH + tid];
            p1 += rp[t * rstr + 2 * CH + tid];
            p2 += rp[t * rstr + 3 * CH + tid];
        }
        sNq[tid] = nq; sNk[tid] = nk; sP1[tid] = p1; sP2[tid] = p2;
    }
    for (int i = tid; i < CH * 128; i += 256) {
        int d = i >> 7, kk = i & 127;
        sW[d * 130 + kk] = w3h[d * Cc + k0 + kk];
    }
    __syncthreads();

    const float tH = temp[h];
#pragma unroll
    for (int e = 0; e < 9; e++) {
        int idx = tid + 256 * e;
        int c = idx / CH, d = idx - c * CH;
        float g = 0.f;
#pragma unroll
        for (int t = 0; t < KT; t++) g += Gp[t * gstr + idx];
        float b1c = sB1[c], b2d = sB2[d];
        float nq = sqrtf(fmaxf(sNq[c] + 2.f * b1c * sP1[c] + 4096.f * b1c * b1c, 0.f));
        float nk = sqrtf(fmaxf(sNk[d] + 2.f * b2d * sP2[d] + 4096.f * b2d * b2d, 0.f));
        g = g + b1c * sP2[d] + b2d * sP1[c] + 4096.f * b1c * b2d;
        sAa[c * 49 + d] = g / (fmaxf(nq, 1e-12f) * fmaxf(nk, 1e-12f)) * tH;
    }
    __syncthreads();

    for (int c = warp * 6; c < warp * 6 + 6; c++) {
        float a0 = sAa[c * 49 + lane];
        float a1 = (lane < 16) ? sAa[c * 49 + 32 + lane] : -3.402823466e38f;
        float m = fmaxf(a0, a1);
#pragma unroll
        for (int o = 16; o; o >>= 1) m = fmaxf(m, __shfl_xor_sync(0xffffffffu, m, o));
        float e0 = __expf(a0 - m);
        float e1 = (lane < 16) ? __expf(a1 - m) : 0.f;
        float s = e0 + e1;
#pragma unroll
        for (int o = 16; o; o >>= 1) s += __shfl_xor_sync(0xffffffffu, s, o);
        float inv = 1.f / s;
        sAa[c * 49 + lane] = e0 * inv;
        if (lane < 16) sAa[c * 49 + 32 + lane] = e1 * inv;
    }
    __syncthreads();

    if (kt == 0 && tid < CH) {
        float s = sB3[tid];
#pragma unroll 8
        for (int d = 0; d < CH; d++) s += sAa[tid * 49 + d] * sB3[d];
        g_mb[b * Cc + h * CH + tid] = s;
    }

    const int kkl = tid & 127, half = tid >> 7;
    float w[CH];
#pragma unroll 12
    for (int d = 0; d < CH; d++) w[d] = sW[d * 130 + kkl];

    __half* Mrow = g_Mh + (size_t)b * Cc * Cc + (size_t)(h * CH) * Cc + k0 + kkl;
    for (int c = half * 24; c < half * 24 + 24; c++) {
        float s = w[0] * sAa[c * 49 + 0] + sW[c * 130 + kkl];
#pragma unroll 12
        for (int d = 1; d < CH; d++) s += sAa[c * 49 + d] * w[d];
        if (h * CH + c == k0 + kkl) s += 1.f;
        Mrow[(size_t)c * Cc] = __float2half_rn(s);
    }
}

// ---------------------------------------------------------------------------
extern "C" void kernel_launch(void* const* d_in, const int* in_sizes, int n_in,
                              void* d_out, int out_size)
{
    (void)in_sizes; (void)n_in; (void)out_size;
    const float* x    = (const float*)d_in[0];
    const float* w1   = (const float*)d_in[1];
    const float* b1   = (const float*)d_in[2];
    const float* w2   = (const float*)d_in[3];
    const float* b2   = (const float*)d_in[4];
    const float* w3   = (const float*)d_in[5];
    const float* b3   = (const float*)d_in[6];
    const float* temp = (const float*)d_in[7];
    float* out = (float*)d_out;

    cudaFuncSetAttribute(gemm_S,   cudaFuncAttributeMaxDynamicSharedMemorySize, DSMEM_S);
    cudaFuncSetAttribute(gemm_U,   cudaFuncAttributeMaxDynamicSharedMemorySize, DSMEM_S);
    cudaFuncSetAttribute(gemm_out, cudaFuncAttributeMaxDynamicSharedMemorySize, DSMEM_O);
    cudaFuncSetAttribute(k_attn1,  cudaFuncAttributeMaxDynamicSharedMemorySize, ATTN1_SM);

    k_convert<<<Bb * Cc, 256>>>(x);
    k_convW<<<dim3(WSZ / 1024, 2), 256>>>(w1, w2);

    gemm_S<<<dim3(6, Bb), 256, DSMEM_S>>>();

    gemm_U<<<dim3(6, 3, Bb), 256, DSMEM_S>>>();

    k_attn1<<<dim3(KT, HEADS, Bb), 256, ATTN1_SM>>>(w1, w2);
    k_foldM<<<dim3(3, HEADS, Bb), 256>>>(w3, b1, b2, b3, temp);

    gemm_out<<<dim3(3, 32, Bb), 256, DSMEM_O>>>(out);
}

// round 14
// speedup vs baseline: 1.1539x; 1.1539x over previous
#include <cuda_runtime.h>
#include <cuda_fp16.h>
#include <math.h>
#include <stdint.h>

#define Bb 16
#define Cc 384
#define Nn 4096
#define HEADS 8
#define CH 48
#define SSZ (Bb*Cc*Cc)
#define WSZ (Cc*Cc)

// ---------------- scratch (device globals; allocation-free) ----------------
__device__ __half g_Sh[SSZ];                // S fp16
__device__ __half g_Mh[SSZ];                // folded (A+I)W3 + I (fp16)
__device__ __half g_Xh[(size_t)Bb*Cc*Nn];   // x fp16 [b][c][n]
__device__ __half g_W1h[WSZ], g_W2h[WSZ];   // weights fp16
__device__ float g_U1[SSZ], g_U2[SSZ];
__device__ float g_Sp[3*Bb*6*16384];        // split-K partial S tiles
__device__ float g_sx[Bb*Cc];               // row sums
__device__ float g_mb[Bb*Cc];
__device__ float g_Gp[3*Bb*HEADS*CH*CH];    // split-K partial Gqk
__device__ float g_rp[3*Bb*HEADS*4*CH];     // split-K partial row reductions

// ---------------- PTX helpers (sm_80-class; no 'a'-gated features) ---------
__device__ __forceinline__ uint32_t smem_u32(const void* p) {
    uint32_t a;
    asm("{ .reg .u64 t; cvta.to.shared.u64 t, %1; cvt.u32.u64 %0, t; }"
        : "=r"(a) : "l"(p));
    return a;
}
__device__ __forceinline__ void ldsm4(uint32_t* r, uint32_t addr) {
    asm volatile("ldmatrix.sync.aligned.m8n8.x4.shared.b16 {%0,%1,%2,%3}, [%4];"
                 : "=r"(r[0]), "=r"(r[1]), "=r"(r[2]), "=r"(r[3]) : "r"(addr));
}
__device__ __forceinline__ void ldsm4t(uint32_t* r, uint32_t addr) {
    asm volatile("ldmatrix.sync.aligned.m8n8.x4.trans.shared.b16 {%0,%1,%2,%3}, [%4];"
                 : "=r"(r[0]), "=r"(r[1]), "=r"(r[2]), "=r"(r[3]) : "r"(addr));
}
__device__ __forceinline__ void mma16816(float* c, const uint32_t* a, const uint32_t* b) {
    asm volatile(
        "mma.sync.aligned.m16n8k16.row.col.f32.f16.f16.f32 "
        "{%0,%1,%2,%3}, {%4,%5,%6,%7}, {%8,%9}, {%0,%1,%2,%3};"
        : "+f"(c[0]), "+f"(c[1]), "+f"(c[2]), "+f"(c[3])
        : "r"(a[0]), "r"(a[1]), "r"(a[2]), "r"(a[3]), "r"(b[0]), "r"(b[1]));
}
#define CP_ASYNC16(dst, src) \
    asm volatile("cp.async.cg.shared.global [%0], [%1], 16;" \
                 :: "r"(dst), "l"(__cvta_generic_to_global(src)))
#define CP_COMMIT() asm volatile("cp.async.commit_group;" ::: "memory")
#define CP_WAIT0()  asm volatile("cp.async.wait_group 0;" ::: "memory")
#define CP_WAIT1()  asm volatile("cp.async.wait_group 1;" ::: "memory")

// smem geometry
#define SROW80    80
#define ATILE     10240
#define STAGE_S1  20480     // Ah, Bh (1-pass NT); 3 stages
#define DSMEM_S   69632
#define AROW144   144
#define ATILE_O   18432
#define BPITCH    272
#define STAGE_O   35840     // 2 stages
#define DSMEM_O   71680
#define ATTN1_SM  49920     // 2 * 48 * 130 * 4

// ---------------------------------------------------------------------------
// compute bodies (warp tile 32x64; acc[2][8][4])
// ---------------------------------------------------------------------------
__device__ __forceinline__ void compute_nt1(uint32_t smb, int wm, int wn, int lane,
                                            float acc[2][8][4]) {
    const int grp = lane >> 3, lr = lane & 7;
#pragma unroll
    for (int ks = 0; ks < 2; ks++) {
        const int kc = ks * 16;
        uint32_t ah[2][4];
#pragma unroll
        for (int ti = 0; ti < 2; ti++) {
            int row = wm * 32 + ti * 16 + lr + (grp & 1) * 8;
            int col = kc + (grp >> 1) * 8;
            ldsm4(ah[ti], smb + row * SROW80 + col * 2);
        }
#pragma unroll
        for (int half = 0; half < 2; half++) {
            uint32_t bhf[4][2];
#pragma unroll
            for (int p = 0; p < 2; p++) {
                int nrow = wn * 64 + half * 32 + p * 16 + (grp >> 1) * 8 + lr;
                int col = kc + (grp & 1) * 8;
                uint32_t r4[4];
                ldsm4(r4, smb + ATILE + nrow * SROW80 + col * 2);
                bhf[2*p][0] = r4[0]; bhf[2*p][1] = r4[1];
                bhf[2*p+1][0] = r4[2]; bhf[2*p+1][1] = r4[3];
            }
#pragma unroll
            for (int ti = 0; ti < 2; ti++)
#pragma unroll
                for (int tj = 0; tj < 4; tj++)
                    mma16816(acc[ti][half * 4 + tj], ah[ti], bhf[tj]);
        }
    }
}

__device__ __forceinline__ void compute_o(uint32_t smbA, uint32_t smbB,
                                          int wm, int wn, int lane,
                                          float acc[2][8][4]) {
    const int grp = lane >> 3, lr = lane & 7;
#pragma unroll
    for (int ks = 0; ks < 4; ks++) {
        const int kc = ks * 16;
        uint32_t ah[2][4];
#pragma unroll
        for (int ti = 0; ti < 2; ti++) {
            int row = wm * 32 + ti * 16 + lr + (grp & 1) * 8;
            int col = kc + (grp >> 1) * 8;
            ldsm4(ah[ti], smbA + row * AROW144 + col * 2);
        }
#pragma unroll
        for (int half = 0; half < 2; half++) {
            uint32_t bhf[4][2];
#pragma unroll
            for (int p = 0; p < 2; p++) {
                int krow = kc + ((lane >> 3) & 1) * 8 + (lane & 7);
                int ncol = wn * 64 + half * 32 + p * 16 + (lane >> 4) * 8;
                uint32_t r4[4];
                ldsm4t(r4, smbB + krow * BPITCH + ncol * 2);
                bhf[2*p][0] = r4[0]; bhf[2*p][1] = r4[1];
                bhf[2*p+1][0] = r4[2]; bhf[2*p+1][1] = r4[3];
            }
#pragma unroll
            for (int ti = 0; ti < 2; ti++)
#pragma unroll
                for (int tj = 0; tj < 4; tj++)
                    mma16816(acc[ti][half * 4 + tj], ah[ti], bhf[tj]);
        }
    }
}

// ---------------------------------------------------------------------------
// k_convert: x -> g_Xh (fp16) + g_sx (row sums). grid (Bb*Cc), 256 thr.
// ---------------------------------------------------------------------------
__global__ void __launch_bounds__(256) k_convert(const float* __restrict__ x) {
    const int row = blockIdx.x;
    const float4* xr = (const float4*)(x + (size_t)row * Nn);
    __half* xo = g_Xh + (size_t)row * Nn;
    float s = 0.f;
#pragma unroll
    for (int j = 0; j < 4; j++) {
        int idx = threadIdx.x + 256 * j;
        float4 v = xr[idx];
        s += (v.x + v.y) + (v.z + v.w);
        __half2 h01 = __floats2half2_rn(v.x, v.y);
        __half2 h23 = __floats2half2_rn(v.z, v.w);
        uint2 hh;
        hh.x = *(uint32_t*)&h01; hh.y = *(uint32_t*)&h23;
        *(uint2*)(xo + idx * 4) = hh;
    }
    __shared__ float red[256];
    red[threadIdx.x] = s;
    __syncthreads();
    for (int o = 128; o; o >>= 1) {
        if (threadIdx.x < o) red[threadIdx.x] += red[threadIdx.x + o];
        __syncthreads();
    }
    if (threadIdx.x == 0) g_sx[row] = red[0];
}

// k_convW: w1,w2 -> fp16. grid (WSZ/1024, 2), 256 thr.
__global__ void __launch_bounds__(256) k_convW(const float* __restrict__ w1,
                                               const float* __restrict__ w2) {
    const float* src = blockIdx.y ? w2 : w1;
    __half* dst = blockIdx.y ? g_W2h : g_W1h;
    int base = blockIdx.x * 1024 + threadIdx.x * 4;
    float4 v = *(const float4*)(src + base);
    __half2 h01 = __floats2half2_rn(v.x, v.y);
    __half2 h23 = __floats2half2_rn(v.z, v.w);
    uint2 hh;
    hh.x = *(uint32_t*)&h01; hh.y = *(uint32_t*)&h23;
    *(uint2*)(dst + base) = hh;
}

// ---------------------------------------------------------------------------
// S GEMM, triangle + split-K=3, 1-pass, cp.async 3-stage, fp16 in.
// grid (6 pairs, 3 kz, 16 batch)
// ---------------------------------------------------------------------------
__global__ void __launch_bounds__(256) gemm_S() {
    extern __shared__ char dsm[];
    const int pxl[6] = {0,0,0,1,1,2}, pyl[6] = {0,1,2,1,2,2};
    const int tid = threadIdx.x, lane = tid & 31, wid = tid >> 5;
    const int wm = wid & 3, wn = wid >> 2;
    const int pair = blockIdx.x, kz = blockIdx.y, bz = blockIdx.z;
    const int bx = pxl[pair], by = pyl[pair];
    const int c0 = (kz == 0) ? 0 : (kz == 1 ? 43 : 86);
    const int c1 = (kz == 0) ? 43 : (kz == 1 ? 86 : 128);
    const int nch = c1 - c0;
    const uint32_t smb = smem_u32(dsm);

    const __half* Ax = g_Xh + ((size_t)bz * Cc + bx * 128) * Nn + c0 * 32;
    const __half* Bx = g_Xh + ((size_t)bz * Cc + by * 128) * Nn + c0 * 32;

    int rw[2], qq[2];
#pragma unroll
    for (int j = 0; j < 2; j++) { int u = tid + 256 * j; rw[j] = u >> 2; qq[j] = u & 3; }

    float acc[2][8][4];
#pragma unroll
    for (int i = 0; i < 2; i++)
#pragma unroll
        for (int j = 0; j < 8; j++)
#pragma unroll
            for (int q = 0; q < 4; q++) acc[i][j][q] = 0.f;

#define ISSUE_S(chunk, stage) do { \
    uint32_t _b = smb + (stage) * STAGE_S1; \
    int _k = (chunk) * 32; \
    _Pragma("unroll") \
    for (int _j = 0; _j < 2; _j++) { \
        CP_ASYNC16(_b + rw[_j] * SROW80 + qq[_j] * 16, \
                   Ax + (size_t)rw[_j] * Nn + _k + qq[_j] * 8); \
        CP_ASYNC16(_b + ATILE + rw[_j] * SROW80 + qq[_j] * 16, \
                   Bx + (size_t)rw[_j] * Nn + _k + qq[_j] * 8); \
    } } while (0)

    ISSUE_S(0, 0); CP_COMMIT();
    ISSUE_S(1, 1); CP_COMMIT();

    int st = 0;
    for (int i = 0; i < nch; i++) {
        if (i == nch - 1) CP_WAIT0(); else CP_WAIT1();
        __syncthreads();
        if (i + 2 < nch) {
            int s2 = st + 2; if (s2 >= 3) s2 -= 3;
            ISSUE_S(i + 2, s2); CP_COMMIT();
        }
        compute_nt1(smb + st * STAGE_S1, wm, wn, lane, acc);
        if (++st == 3) st = 0;
    }
    __syncthreads();
#undef ISSUE_S

    float* sC = (float*)dsm;
#pragma unroll
    for (int ti = 0; ti < 2; ti++)
#pragma unroll
        for (int j = 0; j < 8; j++) {
            int row0 = wm * 32 + ti * 16 + (lane >> 2);
            int col  = wn * 64 + j * 8 + (lane & 3) * 2;
            *(float2*)(sC + row0 * 132 + col)       = make_float2(acc[ti][j][0], acc[ti][j][1]);
            *(float2*)(sC + (row0 + 8) * 132 + col) = make_float2(acc[ti][j][2], acc[ti][j][3]);
        }
    __syncthreads();

    float* outp = g_Sp + (((size_t)kz * Bb + bz) * 6 + pair) * 16384;
    const int r0 = tid >> 1, half = tid & 1;
    const float* src = sC + r0 * 132 + half * 64;
#pragma unroll
    for (int j = 0; j < 64; j += 4)
        *(float4*)(outp + r0 * 128 + half * 64 + j) = *(const float4*)(src + j);
}

// ---------------------------------------------------------------------------
// S reduce: sum 3 partials -> fp16 Sh (tile + transpose).
// grid (16 subtiles, 6 pairs, 16 batch)
// ---------------------------------------------------------------------------
__global__ void __launch_bounds__(256) k_Sreduce() {
    __shared__ float t[32][33];
    const int pxl[6] = {0,0,0,1,1,2}, pyl[6] = {0,1,2,1,2,2};
    const int sub = blockIdx.x, pair = blockIdx.y, bz = blockIdx.z;
    const int px = pxl[pair], py = pyl[pair];
    const int si = sub >> 2, sj = sub & 3;
    const int cc = threadIdx.x & 31, rb = threadIdx.x >> 5;

    const size_t stride = (size_t)Bb * 6 * 16384;
    const float* p0 = g_Sp + ((size_t)bz * 6 + pair) * 16384;
    const float* p1 = p0 + stride;
    const float* p2 = p0 + 2 * stride;
    const size_t gb = (size_t)bz * Cc * Cc;

#pragma unroll
    for (int r = 0; r < 4; r++) {
        int rr = rb + r * 8;
        int li = (si * 32 + rr) * 128 + sj * 32 + cc;
        float s = p0[li] + p1[li] + p2[li];
        t[rr][cc] = s;
        size_t o = gb + (size_t)(px * 128 + si * 32 + rr) * Cc + py * 128 + sj * 32 + cc;
        g_Sh[o] = __float2half_rn(s);
    }
    if (px == py) return;
    __syncthreads();
#pragma unroll
    for (int r = 0; r < 4; r++) {
        int rr = rb + r * 8;
        float s = t[cc][rr];
        size_t o = gb + (size_t)(py * 128 + sj * 32 + rr) * Cc + px * 128 + si * 32 + cc;
        g_Sh[o] = __float2half_rn(s);
    }
}

// ---------------------------------------------------------------------------
// U GEMM (fused U1+U2), 1-pass, cp.async 3-stage, fp16 W. grid (6,3,16).
// ---------------------------------------------------------------------------
__global__ void __launch_bounds__(256) gemm_U() {
    extern __shared__ char dsm[];
    const int tid = threadIdx.x, lane = tid & 31, wid = tid >> 5;
    const int wm = wid & 3, wn = wid >> 2;
    const int sel = blockIdx.x >= 3;
    const int bx = blockIdx.x - (sel ? 3 : 0);
    const int by = blockIdx.y, bz = blockIdx.z;
    const uint32_t smb = smem_u32(dsm);

    const __half* Ax = (sel ? g_W2h : g_W1h) + (size_t)bx * 128 * Cc;
    const __half* Bx = g_Sh + (size_t)bz * Cc * Cc + (size_t)by * 128 * Cc;
    float* Cf = sel ? g_U2 : g_U1;

    int rw[2], qq[2];
#pragma unroll
    for (int j = 0; j < 2; j++) { int u = tid + 256 * j; rw[j] = u >> 2; qq[j] = u & 3; }

    float acc[2][8][4];
#pragma unroll
    for (int i = 0; i < 2; i++)
#pragma unroll
        for (int j = 0; j < 8; j++)
#pragma unroll
            for (int q = 0; q < 4; q++) acc[i][j][q] = 0.f;

#define ISSUE_U(chunk, stage) do { \
    uint32_t _b = smb + (stage) * STAGE_S1; \
    int _k = (chunk) * 32; \
    _Pragma("unroll") \
    for (int _j = 0; _j < 2; _j++) { \
        CP_ASYNC16(_b + rw[_j] * SROW80 + qq[_j] * 16, \
                   Ax + (size_t)rw[_j] * Cc + _k + qq[_j] * 8); \
        CP_ASYNC16(_b + ATILE + rw[_j] * SROW80 + qq[_j] * 16, \
                   Bx + (size_t)rw[_j] * Cc + _k + qq[_j] * 8); \
    } } while (0)

    ISSUE_U(0, 0); CP_COMMIT();
    ISSUE_U(1, 1); CP_COMMIT();

    const int nch = Cc / 32;   // 12
    int st = 0;
    for (int i = 0; i < nch; i++) {
        if (i == nch - 1) CP_WAIT0(); else CP_WAIT1();
        __syncthreads();
        if (i + 2 < nch) {
            int s2 = st + 2; if (s2 >= 3) s2 -= 3;
            ISSUE_U(i + 2, s2); CP_COMMIT();
        }
        compute_nt1(smb + st * STAGE_S1, wm, wn, lane, acc);
        if (++st == 3) st = 0;
    }
    __syncthreads();
#undef ISSUE_U

    float* sC = (float*)dsm;
#pragma unroll
    for (int ti = 0; ti < 2; ti++)
#pragma unroll
        for (int j = 0; j < 8; j++) {
            int row0 = wm * 32 + ti * 16 + (lane >> 2);
            int col  = wn * 64 + j * 8 + (lane & 3) * 2;
            *(float2*)(sC + row0 * 132 + col)       = make_float2(acc[ti][j][0], acc[ti][j][1]);
            *(float2*)(sC + (row0 + 8) * 132 + col) = make_float2(acc[ti][j][2], acc[ti][j][3]);
        }
    __syncthreads();

    const int r0 = tid >> 1, half = tid & 1;
    const float* src = sC + r0 * 132 + half * 64;
    size_t base = ((size_t)bz * Cc + bx * 128 + r0) * Cc + by * 128 + half * 64;
#pragma unroll
    for (int j = 0; j < 64; j += 4)
        *(float4*)(Cf + base + j) = *(const float4*)(src + j);
}

// ---------------------------------------------------------------------------
// out GEMM, 1-pass, BK=64, cp.async 2-stage: out = Mh Xh + mb. grid (3,32,16).
// ---------------------------------------------------------------------------
__global__ void __launch_bounds__(256) gemm_out(float* __restrict__ out)
{
    extern __shared__ char dsm[];
    const int tid = threadIdx.x, lane = tid & 31, wid = tid >> 5;
    const int wm = wid & 3, wn = wid >> 2;
    const int bx = blockIdx.x, by = blockIdx.y, bz = blockIdx.z;
    const uint32_t smb = smem_u32(dsm);

    const __half* pA = g_Mh + (size_t)bz * Cc * Cc + (size_t)bx * 128 * Cc;
    const __half* pB = g_Xh + (size_t)bz * Cc * Nn + by * 128;

    int arw[4], aq[4];
#pragma unroll
    for (int j = 0; j < 4; j++) { int u = tid + 256 * j; arw[j] = u >> 3; aq[j] = u & 7; }
    int brw[4], bq[4];
#pragma unroll
    for (int j = 0; j < 4; j++) { int u = tid + 256 * j; brw[j] = u >> 4; bq[j] = u & 15; }

    float acc[2][8][4];
#pragma unroll
    for (int i = 0; i < 2; i++)
#pragma unroll
        for (int j = 0; j < 8; j++)
#pragma unroll
            for (int q = 0; q < 4; q++) acc[i][j][q] = 0.f;

#define ISSUE_O(chunk, stage) do { \
    uint32_t _b = smb + (stage) * STAGE_O; \
    int _k = (chunk) * 64; \
    _Pragma("unroll") \
    for (int _j = 0; _j < 4; _j++) { \
        CP_ASYNC16(_b + arw[_j] * AROW144 + aq[_j] * 16, \
                   pA + (size_t)arw[_j] * Cc + _k + aq[_j] * 8); \
        CP_ASYNC16(_b + ATILE_O + brw[_j] * BPITCH + bq[_j] * 16, \
                   pB + (size_t)(_k + brw[_j]) * Nn + bq[_j] * 8); \
    } } while (0)

    ISSUE_O(0, 0); CP_COMMIT();

    const int nch = Cc / 64;   // 6
    for (int i = 0; i < nch; i++) {
        CP_WAIT0();
        __syncthreads();
        if (i + 1 < nch) { ISSUE_O(i + 1, (i + 1) & 1); CP_COMMIT(); }
        uint32_t st = smb + (i & 1) * STAGE_O;
        compute_o(st, st + ATILE_O, wm, wn, lane, acc);
    }
    __syncthreads();
#undef ISSUE_O

    float* sC = (float*)dsm;
#pragma unroll
    for (int ti = 0; ti < 2; ti++)
#pragma unroll
        for (int j = 0; j < 8; j++) {
            int row0 = wm * 32 + ti * 16 + (lane >> 2);
            int col  = wn * 64 + j * 8 + (lane & 3) * 2;
            *(float2*)(sC + row0 * 132 + col)       = make_float2(acc[ti][j][0], acc[ti][j][1]);
            *(float2*)(sC + (row0 + 8) * 132 + col) = make_float2(acc[ti][j][2], acc[ti][j][3]);
        }
    __syncthreads();

    const int r0 = tid >> 1, half = tid & 1;
    const float* src = sC + r0 * 132 + half * 64;
    const int grow = bx * 128 + r0;
    float bias = g_mb[bz * Cc + grow];
    size_t base = ((size_t)bz * Cc + grow) * (size_t)Nn + by * 128 + half * 64;
#pragma unroll
    for (int j = 0; j < 64; j += 4) {
        float4 v4 = *(const float4*)(src + j);
        *(float4*)(out + base + j) = make_float4(v4.x + bias, v4.y + bias,
                                                 v4.z + bias, v4.w + bias);
    }
}

// ---------------------------------------------------------------------------
// k_attn1: split-K (3 x 128-wide) partial Gqk + row reductions.
// grid (3, HEADS, Bb).
// ---------------------------------------------------------------------------
__global__ void __launch_bounds__(256) k_attn1(
    const float* __restrict__ w1, const float* __restrict__ w2)
{
    extern __shared__ float satt[];       // sU[48*130], sW[48*130]
    float* sU = satt;
    float* sW = satt + CH * 130;

    const int kt = blockIdx.x, h = blockIdx.y, b = blockIdx.z;
    const int k0 = kt * 128;
    const int tid = threadIdx.x;
    const int warp = tid >> 5, lane = tid & 31;

    const float* U1  = &g_U1[(size_t)b * Cc * Cc + (size_t)h * CH * Cc];
    const float* U2  = &g_U2[(size_t)b * Cc * Cc + (size_t)h * CH * Cc];
    const float* w1h = w1 + (size_t)h * CH * Cc;
    const float* w2h = w2 + (size_t)h * CH * Cc;

    for (int i = tid; i < CH * 128; i += 256) {
        int c = i >> 7, kk = i & 127;
        sU[c * 130 + kk] = U1[c * Cc + k0 + kk];
        sW[c * 130 + kk] = w2h[c * Cc + k0 + kk];
    }
    __syncthreads();

    const int ci0 = (tid >> 4) * 3, di0 = (tid & 15) * 3;
    float acc[3][3];
#pragma unroll
    for (int i = 0; i < 3; i++)
#pragma unroll
        for (int j = 0; j < 3; j++) acc[i][j] = 0.f;
#pragma unroll 8
    for (int kk = 0; kk < 128; kk++) {
        float u[3], w[3];
#pragma unroll
        for (int i = 0; i < 3; i++) u[i] = sU[(ci0 + i) * 130 + kk];
#pragma unroll
        for (int j = 0; j < 3; j++) w[j] = sW[(di0 + j) * 130 + kk];
#pragma unroll
        for (int i = 0; i < 3; i++)
#pragma unroll
            for (int j = 0; j < 3; j++) acc[i][j] += u[i] * w[j];
    }
    float* Gp = g_Gp + (((size_t)kt * Bb + b) * HEADS + h) * (CH * CH);
#pragma unroll
    for (int i = 0; i < 3; i++)
#pragma unroll
        for (int j = 0; j < 3; j++)
            Gp[(ci0 + i) * CH + di0 + j] = acc[i][j];

    float* rp = g_rp + (((size_t)kt * Bb + b) * HEADS + h) * (4 * CH);
    for (int c = warp * 6; c < warp * 6 + 6; c++) {
        float aq = 0.f, ak = 0.f, p1 = 0.f, p2 = 0.f;
#pragma unroll
        for (int it = 0; it < 4; it++) {
            int k = k0 + lane + it * 32;
            float w1v = w1h[c * Cc + k];
            float w2v = w2h[c * Cc + k];
            aq += U1[c * Cc + k] * w1v;
            ak += U2[c * Cc + k] * w2v;
            float sv = g_sx[(size_t)b * Cc + k];
            p1 += w1v * sv;
            p2 += w2v * sv;
        }
#pragma unroll
        for (int o = 16; o; o >>= 1) {
            aq += __shfl_xor_sync(0xffffffffu, aq, o);
            ak += __shfl_xor_sync(0xffffffffu, ak, o);
            p1 += __shfl_xor_sync(0xffffffffu, p1, o);
            p2 += __shfl_xor_sync(0xffffffffu, p2, o);
        }
        if (lane == 0) {
            rp[0 * CH + c] = aq;
            rp[1 * CH + c] = ak;
            rp[2 * CH + c] = p1;
            rp[3 * CH + c] = p2;
        }
    }
}

// ---------------------------------------------------------------------------
// k_foldM: combine partials -> softmax A (redundant per kt), fold M k-slice,
// kt==0 writes mb. grid (3, HEADS, Bb).
// ---------------------------------------------------------------------------
__global__ void __launch_bounds__(256) k_foldM(
    const float* __restrict__ w3, const float* __restrict__ b1,
    const float* __restrict__ b2, const float* __restrict__ b3,
    const float* __restrict__ temp)
{
    __shared__ float sAa[CH * 49];
    __shared__ float sW[CH * 130];
    __shared__ float sNq[CH], sNk[CH], sP1[CH], sP2[CH];
    __shared__ float sB1[CH], sB2[CH], sB3[CH];

    const int kt = blockIdx.x, h = blockIdx.y, b = blockIdx.z;
    const int k0 = kt * 128;
    const int tid = threadIdx.x;
    const int warp = tid >> 5, lane = tid & 31;

    const size_t gstr = (size_t)Bb * HEADS * CH * CH;
    const size_t rstr = (size_t)Bb * HEADS * 4 * CH;
    const float* Gp = g_Gp + ((size_t)b * HEADS + h) * (CH * CH);
    const float* rp = g_rp + ((size_t)b * HEADS + h) * (4 * CH);
    const float* w3h = w3 + (size_t)h * CH * Cc;

    if (tid < CH) {
        sB1[tid] = b1[h * CH + tid];
        sB2[tid] = b2[h * CH + tid];
        sB3[tid] = b3[h * CH + tid];
        sNq[tid] = rp[0 * CH + tid] + rp[rstr + 0 * CH + tid] + rp[2 * rstr + 0 * CH + tid];
        sNk[tid] = rp[1 * CH + tid] + rp[rstr + 1 * CH + tid] + rp[2 * rstr + 1 * CH + tid];
        sP1[tid] = rp[2 * CH + tid] + rp[rstr + 2 * CH + tid] + rp[2 * rstr + 2 * CH + tid];
        sP2[tid] = rp[3 * CH + tid] + rp[rstr + 3 * CH + tid] + rp[2 * rstr + 3 * CH + tid];
    }
    for (int i = tid; i < CH * 128; i += 256) {
        int d = i >> 7, kk = i & 127;
        sW[d * 130 + kk] = w3h[d * Cc + k0 + kk];
    }
    __syncthreads();

    const float tH = temp[h];
#pragma unroll
    for (int e = 0; e < 9; e++) {
        int idx = tid + 256 * e;
        int c = idx / CH, d = idx - c * CH;
        float g = Gp[idx] + Gp[gstr + idx] + Gp[2 * gstr + idx];
        float b1c = sB1[c], b2d = sB2[d];
        float nq = sqrtf(fmaxf(sNq[c] + 2.f * b1c * sP1[c] + 4096.f * b1c * b1c, 0.f));
        float nk = sqrtf(fmaxf(sNk[d] + 2.f * b2d * sP2[d] + 4096.f * b2d * b2d, 0.f));
        g = g + b1c * sP2[d] + b2d * sP1[c] + 4096.f * b1c * b2d;
        sAa[c * 49 + d] = g / (fmaxf(nq, 1e-12f) * fmaxf(nk, 1e-12f)) * tH;
    }
    __syncthreads();

    for (int c = warp * 6; c < warp * 6 + 6; c++) {
        float a0 = sAa[c * 49 + lane];
        float a1 = (lane < 16) ? sAa[c * 49 + 32 + lane] : -3.402823466e38f;
        float m = fmaxf(a0, a1);
#pragma unroll
        for (int o = 16; o; o >>= 1) m = fmaxf(m, __shfl_xor_sync(0xffffffffu, m, o));
        float e0 = __expf(a0 - m);
        float e1 = (lane < 16) ? __expf(a1 - m) : 0.f;
        float s = e0 + e1;
#pragma unroll
        for (int o = 16; o; o >>= 1) s += __shfl_xor_sync(0xffffffffu, s, o);
        float inv = 1.f / s;
        sAa[c * 49 + lane] = e0 * inv;
        if (lane < 16) sAa[c * 49 + 32 + lane] = e1 * inv;
    }
    __syncthreads();

    if (kt == 0 && tid < CH) {
        float s = sB3[tid];
#pragma unroll 8
        for (int d = 0; d < CH; d++) s += sAa[tid * 49 + d] * sB3[d];
        g_mb[b * Cc + h * CH + tid] = s;
    }

    const int kkl = tid & 127, half = tid >> 7;
    float w[CH];
#pragma unroll 12
    for (int d = 0; d < CH; d++) w[d] = sW[d * 130 + kkl];

    __half* Mrow = g_Mh + (size_t)b * Cc * Cc + (size_t)(h * CH) * Cc + k0 + kkl;
    for (int c = half * 24; c < half * 24 + 24; c++) {
        float s = w[0] * sAa[c * 49 + 0] + sW[c * 130 + kkl];
#pragma unroll 12
        for (int d = 1; d < CH; d++) s += sAa[c * 49 + d] * w[d];
        if (h * CH + c == k0 + kkl) s += 1.f;
        Mrow[(size_t)c * Cc] = __float2half_rn(s);
    }
}

// ---------------------------------------------------------------------------
extern "C" void kernel_launch(void* const* d_in, const int* in_sizes, int n_in,
                              void* d_out, int out_size)
{
    (void)in_sizes; (void)n_in; (void)out_size;
    const float* x    = (const float*)d_in[0];
    const float* w1   = (const float*)d_in[1];
    const float* b1   = (const float*)d_in[2];
    const float* w2   = (const float*)d_in[3];
    const float* b2   = (const float*)d_in[4];
    const float* w3   = (const float*)d_in[5];
    const float* b3   = (const float*)d_in[6];
    const float* temp = (const float*)d_in[7];
    float* out = (float*)d_out;

    cudaFuncSetAttribute(gemm_S,   cudaFuncAttributeMaxDynamicSharedMemorySize, DSMEM_S);
    cudaFuncSetAttribute(gemm_U,   cudaFuncAttributeMaxDynamicSharedMemorySize, DSMEM_S);
    cudaFuncSetAttribute(gemm_out, cudaFuncAttributeMaxDynamicSharedMemorySize, DSMEM_O);
    cudaFuncSetAttribute(k_attn1,  cudaFuncAttributeMaxDynamicSharedMemorySize, ATTN1_SM);

    k_convert<<<Bb * Cc, 256>>>(x);
    k_convW<<<dim3(WSZ / 1024, 2), 256>>>(w1, w2);

    gemm_S<<<dim3(6, 3, Bb), 256, DSMEM_S>>>();
    k_Sreduce<<<dim3(16, 6, Bb), 256>>>();

    gemm_U<<<dim3(6, 3, Bb), 256, DSMEM_S>>>();

    k_attn1<<<dim3(3, HEADS, Bb), 256, ATTN1_SM>>>(w1, w2);
    k_foldM<<<dim3(3, HEADS, Bb), 256>>>(w3, b1, b2, b3, temp);

    gemm_out<<<dim3(3, 32, Bb), 256, DSMEM_O>>>(out);
}

// round 15
// speedup vs baseline: 1.1740x; 1.0174x over previous
#include <cuda_runtime.h>
#include <cuda_fp16.h>
#include <math.h>
#include <stdint.h>

#define Bb 16
#define Cc 384
#define Nn 4096
#define HEADS 8
#define CH 48
#define SSZ (Bb*Cc*Cc)
#define WSZ (Cc*Cc)

// ---------------- scratch (device globals; allocation-free) ----------------
__device__ __half g_Sh[SSZ];                // S fp16
__device__ __half g_Mh[SSZ];                // folded (A+I)W3 + I (fp16)
__device__ __half g_Xh[(size_t)Bb*Cc*Nn];   // x fp16 [b][c][n]
__device__ __half g_W1h[WSZ], g_W2h[WSZ];   // weights fp16
__device__ float g_U1[SSZ], g_U2[SSZ];
__device__ float g_Sp[3*Bb*6*16384];        // split-K partial S tiles
__device__ float g_sx[Bb*Cc];               // row sums
__device__ float g_mb[Bb*Cc];
__device__ float g_Gp[3*Bb*HEADS*CH*CH];    // split-K partial Gqk
__device__ float g_rp[3*Bb*HEADS*4*CH];     // split-K partial row reductions

// ---------------- PTX helpers (sm_80-class; no 'a'-gated features) ---------
__device__ __forceinline__ uint32_t smem_u32(const void* p) {
    uint32_t a;
    asm("{ .reg .u64 t; cvta.to.shared.u64 t, %1; cvt.u32.u64 %0, t; }"
        : "=r"(a) : "l"(p));
    return a;
}
__device__ __forceinline__ void ldsm4(uint32_t* r, uint32_t addr) {
    asm volatile("ldmatrix.sync.aligned.m8n8.x4.shared.b16 {%0,%1,%2,%3}, [%4];"
                 : "=r"(r[0]), "=r"(r[1]), "=r"(r[2]), "=r"(r[3]) : "r"(addr));
}
__device__ __forceinline__ void ldsm4t(uint32_t* r, uint32_t addr) {
    asm volatile("ldmatrix.sync.aligned.m8n8.x4.trans.shared.b16 {%0,%1,%2,%3}, [%4];"
                 : "=r"(r[0]), "=r"(r[1]), "=r"(r[2]), "=r"(r[3]) : "r"(addr));
}
__device__ __forceinline__ void mma16816(float* c, const uint32_t* a, const uint32_t* b) {
    asm volatile(
        "mma.sync.aligned.m16n8k16.row.col.f32.f16.f16.f32 "
        "{%0,%1,%2,%3}, {%4,%5,%6,%7}, {%8,%9}, {%0,%1,%2,%3};"
        : "+f"(c[0]), "+f"(c[1]), "+f"(c[2]), "+f"(c[3])
        : "r"(a[0]), "r"(a[1]), "r"(a[2]), "r"(a[3]), "r"(b[0]), "r"(b[1]));
}
#define CP_ASYNC16(dst, src) \
    asm volatile("cp.async.cg.shared.global [%0], [%1], 16;" \
                 :: "r"(dst), "l"(__cvta_generic_to_global(src)))
#define CP_COMMIT() asm volatile("cp.async.commit_group;" ::: "memory")
#define CP_WAIT0()  asm volatile("cp.async.wait_group 0;" ::: "memory")
#define CP_WAIT1()  asm volatile("cp.async.wait_group 1;" ::: "memory")

// smem geometry
#define SROW80    80
#define ATILE     10240
#define STAGE_S1  20480     // Ah, Bh (1-pass NT); 3 stages
#define DSMEM_S   69632
#define BPITCH    272
#define BTILE32   8704      // 32 * 272
#define STAGE_O32 18944     // ATILE + BTILE32; 2 stages
#define DSMEM_O   37888
#define ATTN1_SM  49920     // 2 * 48 * 130 * 4

// ---------------------------------------------------------------------------
// compute bodies (warp tile 32x64; acc[2][8][4])
// ---------------------------------------------------------------------------
__device__ __forceinline__ void compute_nt1(uint32_t smb, int wm, int wn, int lane,
                                            float acc[2][8][4]) {
    const int grp = lane >> 3, lr = lane & 7;
#pragma unroll
    for (int ks = 0; ks < 2; ks++) {
        const int kc = ks * 16;
        uint32_t ah[2][4];
#pragma unroll
        for (int ti = 0; ti < 2; ti++) {
            int row = wm * 32 + ti * 16 + lr + (grp & 1) * 8;
            int col = kc + (grp >> 1) * 8;
            ldsm4(ah[ti], smb + row * SROW80 + col * 2);
        }
#pragma unroll
        for (int half = 0; half < 2; half++) {
            uint32_t bhf[4][2];
#pragma unroll
            for (int p = 0; p < 2; p++) {
                int nrow = wn * 64 + half * 32 + p * 16 + (grp >> 1) * 8 + lr;
                int col = kc + (grp & 1) * 8;
                uint32_t r4[4];
                ldsm4(r4, smb + ATILE + nrow * SROW80 + col * 2);
                bhf[2*p][0] = r4[0]; bhf[2*p][1] = r4[1];
                bhf[2*p+1][0] = r4[2]; bhf[2*p+1][1] = r4[3];
            }
#pragma unroll
            for (int ti = 0; ti < 2; ti++)
#pragma unroll
                for (int tj = 0; tj < 4; tj++)
                    mma16816(acc[ti][half * 4 + tj], ah[ti], bhf[tj]);
        }
    }
}

// BK=32 trans-B compute: A at smbA (pitch 80), B at smbB (32 krows, pitch 272)
__device__ __forceinline__ void compute_o32(uint32_t smbA, uint32_t smbB,
                                            int wm, int wn, int lane,
                                            float acc[2][8][4]) {
    const int grp = lane >> 3, lr = lane & 7;
#pragma unroll
    for (int ks = 0; ks < 2; ks++) {
        const int kc = ks * 16;
        uint32_t ah[2][4];
#pragma unroll
        for (int ti = 0; ti < 2; ti++) {
            int row = wm * 32 + ti * 16 + lr + (grp & 1) * 8;
            int col = kc + (grp >> 1) * 8;
            ldsm4(ah[ti], smbA + row * SROW80 + col * 2);
        }
#pragma unroll
        for (int half = 0; half < 2; half++) {
            uint32_t bhf[4][2];
#pragma unroll
            for (int p = 0; p < 2; p++) {
                int krow = kc + ((lane >> 3) & 1) * 8 + (lane & 7);
                int ncol = wn * 64 + half * 32 + p * 16 + (lane >> 4) * 8;
                uint32_t r4[4];
                ldsm4t(r4, smbB + krow * BPITCH + ncol * 2);
                bhf[2*p][0] = r4[0]; bhf[2*p][1] = r4[1];
                bhf[2*p+1][0] = r4[2]; bhf[2*p+1][1] = r4[3];
            }
#pragma unroll
            for (int ti = 0; ti < 2; ti++)
#pragma unroll
                for (int tj = 0; tj < 4; tj++)
                    mma16816(acc[ti][half * 4 + tj], ah[ti], bhf[tj]);
        }
    }
}

// ---------------------------------------------------------------------------
// k_convert: x -> g_Xh (fp16) + g_sx (row sums). grid (Bb*Cc), 256 thr.
// ---------------------------------------------------------------------------
__global__ void __launch_bounds__(256) k_convert(const float* __restrict__ x) {
    const int row = blockIdx.x;
    const float4* xr = (const float4*)(x + (size_t)row * Nn);
    __half* xo = g_Xh + (size_t)row * Nn;
    float s = 0.f;
#pragma unroll
    for (int j = 0; j < 4; j++) {
        int idx = threadIdx.x + 256 * j;
        float4 v = xr[idx];
        s += (v.x + v.y) + (v.z + v.w);
        __half2 h01 = __floats2half2_rn(v.x, v.y);
        __half2 h23 = __floats2half2_rn(v.z, v.w);
        uint2 hh;
        hh.x = *(uint32_t*)&h01; hh.y = *(uint32_t*)&h23;
        *(uint2*)(xo + idx * 4) = hh;
    }
    __shared__ float red[256];
    red[threadIdx.x] = s;
    __syncthreads();
    for (int o = 128; o; o >>= 1) {
        if (threadIdx.x < o) red[threadIdx.x] += red[threadIdx.x + o];
        __syncthreads();
    }
    if (threadIdx.x == 0) g_sx[row] = red[0];
}

// k_convW: w1,w2 -> fp16. grid (WSZ/1024, 2), 256 thr.
__global__ void __launch_bounds__(256) k_convW(const float* __restrict__ w1,
                                               const float* __restrict__ w2) {
    const float* src = blockIdx.y ? w2 : w1;
    __half* dst = blockIdx.y ? g_W2h : g_W1h;
    int base = blockIdx.x * 1024 + threadIdx.x * 4;
    float4 v = *(const float4*)(src + base);
    __half2 h01 = __floats2half2_rn(v.x, v.y);
    __half2 h23 = __floats2half2_rn(v.z, v.w);
    uint2 hh;
    hh.x = *(uint32_t*)&h01; hh.y = *(uint32_t*)&h23;
    *(uint2*)(dst + base) = hh;
}

// ---------------------------------------------------------------------------
// S GEMM, triangle + split-K=3, 1-pass, cp.async 3-stage, fp16 in.
// grid (6 pairs, 3 kz, 16 batch)
// ---------------------------------------------------------------------------
__global__ void __launch_bounds__(256) gemm_S() {
    extern __shared__ char dsm[];
    const int pxl[6] = {0,0,0,1,1,2}, pyl[6] = {0,1,2,1,2,2};
    const int tid = threadIdx.x, lane = tid & 31, wid = tid >> 5;
    const int wm = wid & 3, wn = wid >> 2;
    const int pair = blockIdx.x, kz = blockIdx.y, bz = blockIdx.z;
    const int bx = pxl[pair], by = pyl[pair];
    const int c0 = (kz == 0) ? 0 : (kz == 1 ? 43 : 86);
    const int c1 = (kz == 0) ? 43 : (kz == 1 ? 86 : 128);
    const int nch = c1 - c0;
    const uint32_t smb = smem_u32(dsm);

    const __half* Ax = g_Xh + ((size_t)bz * Cc + bx * 128) * Nn + c0 * 32;
    const __half* Bx = g_Xh + ((size_t)bz * Cc + by * 128) * Nn + c0 * 32;

    int rw[2], qq[2];
#pragma unroll
    for (int j = 0; j < 2; j++) { int u = tid + 256 * j; rw[j] = u >> 2; qq[j] = u & 3; }

    float acc[2][8][4];
#pragma unroll
    for (int i = 0; i < 2; i++)
#pragma unroll
        for (int j = 0; j < 8; j++)
#pragma unroll
            for (int q = 0; q < 4; q++) acc[i][j][q] = 0.f;

#define ISSUE_S(chunk, stage) do { \
    uint32_t _b = smb + (stage) * STAGE_S1; \
    int _k = (chunk) * 32; \
    _Pragma("unroll") \
    for (int _j = 0; _j < 2; _j++) { \
        CP_ASYNC16(_b + rw[_j] * SROW80 + qq[_j] * 16, \
                   Ax + (size_t)rw[_j] * Nn + _k + qq[_j] * 8); \
        CP_ASYNC16(_b + ATILE + rw[_j] * SROW80 + qq[_j] * 16, \
                   Bx + (size_t)rw[_j] * Nn + _k + qq[_j] * 8); \
    } } while (0)

    ISSUE_S(0, 0); CP_COMMIT();
    ISSUE_S(1, 1); CP_COMMIT();

    int st = 0;
    for (int i = 0; i < nch; i++) {
        if (i == nch - 1) CP_WAIT0(); else CP_WAIT1();
        __syncthreads();
        if (i + 2 < nch) {
            int s2 = st + 2; if (s2 >= 3) s2 -= 3;
            ISSUE_S(i + 2, s2); CP_COMMIT();
        }
        compute_nt1(smb + st * STAGE_S1, wm, wn, lane, acc);
        if (++st == 3) st = 0;
    }
    __syncthreads();
#undef ISSUE_S

    float* sC = (float*)dsm;
#pragma unroll
    for (int ti = 0; ti < 2; ti++)
#pragma unroll
        for (int j = 0; j < 8; j++) {
            int row0 = wm * 32 + ti * 16 + (lane >> 2);
            int col  = wn * 64 + j * 8 + (lane & 3) * 2;
            *(float2*)(sC + row0 * 132 + col)       = make_float2(acc[ti][j][0], acc[ti][j][1]);
            *(float2*)(sC + (row0 + 8) * 132 + col) = make_float2(acc[ti][j][2], acc[ti][j][3]);
        }
    __syncthreads();

    float* outp = g_Sp + (((size_t)kz * Bb + bz) * 6 + pair) * 16384;
    const int r0 = tid >> 1, half = tid & 1;
    const float* src = sC + r0 * 132 + half * 64;
#pragma unroll
    for (int j = 0; j < 64; j += 4)
        *(float4*)(outp + r0 * 128 + half * 64 + j) = *(const float4*)(src + j);
}

// ---------------------------------------------------------------------------
// S reduce: sum 3 partials -> fp16 Sh (tile + transpose).
// grid (16 subtiles, 6 pairs, 16 batch)
// ---------------------------------------------------------------------------
__global__ void __launch_bounds__(256) k_Sreduce() {
    __shared__ float t[32][33];
    const int pxl[6] = {0,0,0,1,1,2}, pyl[6] = {0,1,2,1,2,2};
    const int sub = blockIdx.x, pair = blockIdx.y, bz = blockIdx.z;
    const int px = pxl[pair], py = pyl[pair];
    const int si = sub >> 2, sj = sub & 3;
    const int cc = threadIdx.x & 31, rb = threadIdx.x >> 5;

    const size_t stride = (size_t)Bb * 6 * 16384;
    const float* p0 = g_Sp + ((size_t)bz * 6 + pair) * 16384;
    const float* p1 = p0 + stride;
    const float* p2 = p0 + 2 * stride;
    const size_t gb = (size_t)bz * Cc * Cc;

#pragma unroll
    for (int r = 0; r < 4; r++) {
        int rr = rb + r * 8;
        int li = (si * 32 + rr) * 128 + sj * 32 + cc;
        float s = p0[li] + p1[li] + p2[li];
        t[rr][cc] = s;
        size_t o = gb + (size_t)(px * 128 + si * 32 + rr) * Cc + py * 128 + sj * 32 + cc;
        g_Sh[o] = __float2half_rn(s);
    }
    if (px == py) return;
    __syncthreads();
#pragma unroll
    for (int r = 0; r < 4; r++) {
        int rr = rb + r * 8;
        float s = t[cc][rr];
        size_t o = gb + (size_t)(py * 128 + sj * 32 + rr) * Cc + px * 128 + si * 32 + cc;
        g_Sh[o] = __float2half_rn(s);
    }
}

// ---------------------------------------------------------------------------
// U GEMM (fused U1+U2), 1-pass, cp.async 3-stage, fp16 W. grid (6,3,16).
// ---------------------------------------------------------------------------
__global__ void __launch_bounds__(256) gemm_U() {
    extern __shared__ char dsm[];
    const int tid = threadIdx.x, lane = tid & 31, wid = tid >> 5;
    const int wm = wid & 3, wn = wid >> 2;
    const int sel = blockIdx.x >= 3;
    const int bx = blockIdx.x - (sel ? 3 : 0);
    const int by = blockIdx.y, bz = blockIdx.z;
    const uint32_t smb = smem_u32(dsm);

    const __half* Ax = (sel ? g_W2h : g_W1h) + (size_t)bx * 128 * Cc;
    const __half* Bx = g_Sh + (size_t)bz * Cc * Cc + (size_t)by * 128 * Cc;
    float* Cf = sel ? g_U2 : g_U1;

    int rw[2], qq[2];
#pragma unroll
    for (int j = 0; j < 2; j++) { int u = tid + 256 * j; rw[j] = u >> 2; qq[j] = u & 3; }

    float acc[2][8][4];
#pragma unroll
    for (int i = 0; i < 2; i++)
#pragma unroll
        for (int j = 0; j < 8; j++)
#pragma unroll
            for (int q = 0; q < 4; q++) acc[i][j][q] = 0.f;

#define ISSUE_U(chunk, stage) do { \
    uint32_t _b = smb + (stage) * STAGE_S1; \
    int _k = (chunk) * 32; \
    _Pragma("unroll") \
    for (int _j = 0; _j < 2; _j++) { \
        CP_ASYNC16(_b + rw[_j] * SROW80 + qq[_j] * 16, \
                   Ax + (size_t)rw[_j] * Cc + _k + qq[_j] * 8); \
        CP_ASYNC16(_b + ATILE + rw[_j] * SROW80 + qq[_j] * 16, \
                   Bx + (size_t)rw[_j] * Cc + _k + qq[_j] * 8); \
    } } while (0)

    ISSUE_U(0, 0); CP_COMMIT();
    ISSUE_U(1, 1); CP_COMMIT();

    const int nch = Cc / 32;   // 12
    int st = 0;
    for (int i = 0; i < nch; i++) {
        if (i == nch - 1) CP_WAIT0(); else CP_WAIT1();
        __syncthreads();
        if (i + 2 < nch) {
            int s2 = st + 2; if (s2 >= 3) s2 -= 3;
            ISSUE_U(i + 2, s2); CP_COMMIT();
        }
        compute_nt1(smb + st * STAGE_S1, wm, wn, lane, acc);
        if (++st == 3) st = 0;
    }
    __syncthreads();
#undef ISSUE_U

    float* sC = (float*)dsm;
#pragma unroll
    for (int ti = 0; ti < 2; ti++)
#pragma unroll
        for (int j = 0; j < 8; j++) {
            int row0 = wm * 32 + ti * 16 + (lane >> 2);
            int col  = wn * 64 + j * 8 + (lane & 3) * 2;
            *(float2*)(sC + row0 * 132 + col)       = make_float2(acc[ti][j][0], acc[ti][j][1]);
            *(float2*)(sC + (row0 + 8) * 132 + col) = make_float2(acc[ti][j][2], acc[ti][j][3]);
        }
    __syncthreads();

    const int r0 = tid >> 1, half = tid & 1;
    const float* src = sC + r0 * 132 + half * 64;
    size_t base = ((size_t)bz * Cc + bx * 128 + r0) * Cc + by * 128 + half * 64;
#pragma unroll
    for (int j = 0; j < 64; j += 4)
        *(float4*)(Cf + base + j) = *(const float4*)(src + j);
}

// ---------------------------------------------------------------------------
// out GEMM, 1-pass, BK=32, cp.async 2-stage, 2 blocks/SM (smem 37.9KB):
// out = Mh Xh + mb. Epilogue in two 64-row passes. grid (3,32,16).
// ---------------------------------------------------------------------------
__global__ void __launch_bounds__(256) gemm_out(float* __restrict__ out)
{
    extern __shared__ char dsm[];
    const int tid = threadIdx.x, lane = tid & 31, wid = tid >> 5;
    const int wm = wid & 3, wn = wid >> 2;
    const int bx = blockIdx.x, by = blockIdx.y, bz = blockIdx.z;
    const uint32_t smb = smem_u32(dsm);

    const __half* pA = g_Mh + (size_t)bz * Cc * Cc + (size_t)bx * 128 * Cc;
    const __half* pB = g_Xh + (size_t)bz * Cc * Nn + by * 128;

    // A loader: 128 rows x 32 fp16 = 512 x 16B -> 2/thread
    int arw[2], aq[2];
#pragma unroll
    for (int j = 0; j < 2; j++) { int u = tid + 256 * j; arw[j] = u >> 2; aq[j] = u & 3; }
    // B loader: 32 krows x 128 fp16 = 512 x 16B -> 2/thread
    int brw[2], bq[2];
#pragma unroll
    for (int j = 0; j < 2; j++) { int u = tid + 256 * j; brw[j] = u >> 4; bq[j] = u & 15; }

    float acc[2][8][4];
#pragma unroll
    for (int i = 0; i < 2; i++)
#pragma unroll
        for (int j = 0; j < 8; j++)
#pragma unroll
            for (int q = 0; q < 4; q++) acc[i][j][q] = 0.f;

#define ISSUE_O(chunk, stage) do { \
    uint32_t _b = smb + (stage) * STAGE_O32; \
    int _k = (chunk) * 32; \
    _Pragma("unroll") \
    for (int _j = 0; _j < 2; _j++) { \
        CP_ASYNC16(_b + arw[_j] * SROW80 + aq[_j] * 16, \
                   pA + (size_t)arw[_j] * Cc + _k + aq[_j] * 8); \
        CP_ASYNC16(_b + ATILE + brw[_j] * BPITCH + bq[_j] * 16, \
                   pB + (size_t)(_k + brw[_j]) * Nn + bq[_j] * 8); \
    } } while (0)

    ISSUE_O(0, 0); CP_COMMIT();

    const int nch = Cc / 32;   // 12
    for (int i = 0; i < nch; i++) {
        CP_WAIT0();
        __syncthreads();
        if (i + 1 < nch) { ISSUE_O(i + 1, (i + 1) & 1); CP_COMMIT(); }
        uint32_t st = smb + (i & 1) * STAGE_O32;
        compute_o32(st, st + ATILE, wm, wn, lane, acc);
    }
#undef ISSUE_O

    // epilogue: two 64-row passes through smem (fits 37.9KB budget)
    float* sC = (float*)dsm;
#pragma unroll
    for (int hp = 0; hp < 2; hp++) {
        __syncthreads();
        if ((wm >> 1) == hp) {
            const int lrow = (wm & 1) * 32;
#pragma unroll
            for (int ti = 0; ti < 2; ti++)
#pragma unroll
                for (int j = 0; j < 8; j++) {
                    int row0 = lrow + ti * 16 + (lane >> 2);
                    int col  = wn * 64 + j * 8 + (lane & 3) * 2;
                    *(float2*)(sC + row0 * 132 + col)       = make_float2(acc[ti][j][0], acc[ti][j][1]);
                    *(float2*)(sC + (row0 + 8) * 132 + col) = make_float2(acc[ti][j][2], acc[ti][j][3]);
                }
        }
        __syncthreads();
        const int row = tid >> 2, quad = tid & 3;   // 64 rows x 4 quarters
        const float* src = sC + row * 132 + quad * 32;
        const int grow = bx * 128 + hp * 64 + row;
        float bias = g_mb[bz * Cc + grow];
        float* dst = out + ((size_t)bz * Cc + grow) * (size_t)Nn + by * 128 + quad * 32;
#pragma unroll
        for (int j = 0; j < 32; j += 4) {
            float4 v4 = *(const float4*)(src + j);
            *(float4*)(dst + j) = make_float4(v4.x + bias, v4.y + bias,
                                              v4.z + bias, v4.w + bias);
        }
    }
}

// ---------------------------------------------------------------------------
// k_attn1: split-K (3 x 128-wide) partial Gqk + row reductions.
// grid (3, HEADS, Bb).
// ---------------------------------------------------------------------------
__global__ void __launch_bounds__(256) k_attn1(
    const float* __restrict__ w1, const float* __restrict__ w2)
{
    extern __shared__ float satt[];       // sU[48*130], sW[48*130]
    float* sU = satt;
    float* sW = satt + CH * 130;

    const int kt = blockIdx.x, h = blockIdx.y, b = blockIdx.z;
    const int k0 = kt * 128;
    const int tid = threadIdx.x;
    const int warp = tid >> 5, lane = tid & 31;

    const float* U1  = &g_U1[(size_t)b * Cc * Cc + (size_t)h * CH * Cc];
    const float* U2  = &g_U2[(size_t)b * Cc * Cc + (size_t)h * CH * Cc];
    const float* w1h = w1 + (size_t)h * CH * Cc;
    const float* w2h = w2 + (size_t)h * CH * Cc;

    for (int i = tid; i < CH * 128; i += 256) {
        int c = i >> 7, kk = i & 127;
        sU[c * 130 + kk] = U1[c * Cc + k0 + kk];
        sW[c * 130 + kk] = w2h[c * Cc + k0 + kk];
    }
    __syncthreads();

    const int ci0 = (tid >> 4) * 3, di0 = (tid & 15) * 3;
    float acc[3][3];
#pragma unroll
    for (int i = 0; i < 3; i++)
#pragma unroll
        for (int j = 0; j < 3; j++) acc[i][j] = 0.f;
#pragma unroll 8
    for (int kk = 0; kk < 128; kk++) {
        float u[3], w[3];
#pragma unroll
        for (int i = 0; i < 3; i++) u[i] = sU[(ci0 + i) * 130 + kk];
#pragma unroll
        for (int j = 0; j < 3; j++) w[j] = sW[(di0 + j) * 130 + kk];
#pragma unroll
        for (int i = 0; i < 3; i++)
#pragma unroll
            for (int j = 0; j < 3; j++) acc[i][j] += u[i] * w[j];
    }
    float* Gp = g_Gp + (((size_t)kt * Bb + b) * HEADS + h) * (CH * CH);
#pragma unroll
    for (int i = 0; i < 3; i++)
#pragma unroll
        for (int j = 0; j < 3; j++)
            Gp[(ci0 + i) * CH + di0 + j] = acc[i][j];

    float* rp = g_rp + (((size_t)kt * Bb + b) * HEADS + h) * (4 * CH);
    for (int c = warp * 6; c < warp * 6 + 6; c++) {
        float aq = 0.f, ak = 0.f, p1 = 0.f, p2 = 0.f;
#pragma unroll
        for (int it = 0; it < 4; it++) {
            int k = k0 + lane + it * 32;
            float w1v = w1h[c * Cc + k];
            float w2v = w2h[c * Cc + k];
            aq += U1[c * Cc + k] * w1v;
            ak += U2[c * Cc + k] * w2v;
            float sv = g_sx[(size_t)b * Cc + k];
            p1 += w1v * sv;
            p2 += w2v * sv;
        }
#pragma unroll
        for (int o = 16; o; o >>= 1) {
            aq += __shfl_xor_sync(0xffffffffu, aq, o);
            ak += __shfl_xor_sync(0xffffffffu, ak, o);
            p1 += __shfl_xor_sync(0xffffffffu, p1, o);
            p2 += __shfl_xor_sync(0xffffffffu, p2, o);
        }
        if (lane == 0) {
            rp[0 * CH + c] = aq;
            rp[1 * CH + c] = ak;
            rp[2 * CH + c] = p1;
            rp[3 * CH + c] = p2;
        }
    }
}

// ---------------------------------------------------------------------------
// k_foldM: combine partials -> softmax A (redundant per kt), fold M k-slice,
// kt==0 writes mb. grid (3, HEADS, Bb).
// ---------------------------------------------------------------------------
__global__ void __launch_bounds__(256) k_foldM(
    const float* __restrict__ w3, const float* __restrict__ b1,
    const float* __restrict__ b2, const float* __restrict__ b3,
    const float* __restrict__ temp)
{
    __shared__ float sAa[CH * 49];
    __shared__ float sW[CH * 130];
    __shared__ float sNq[CH], sNk[CH], sP1[CH], sP2[CH];
    __shared__ float sB1[CH], sB2[CH], sB3[CH];

    const int kt = blockIdx.x, h = blockIdx.y, b = blockIdx.z;
    const int k0 = kt * 128;
    const int tid = threadIdx.x;
    const int warp = tid >> 5, lane = tid & 31;

    const size_t gstr = (size_t)Bb * HEADS * CH * CH;
    const size_t rstr = (size_t)Bb * HEADS * 4 * CH;
    const float* Gp = g_Gp + ((size_t)b * HEADS + h) * (CH * CH);
    const float* rp = g_rp + ((size_t)b * HEADS + h) * (4 * CH);
    const float* w3h = w3 + (size_t)h * CH * Cc;

    if (tid < CH) {
        sB1[tid] = b1[h * CH + tid];
        sB2[tid] = b2[h * CH + tid];
        sB3[tid] = b3[h * CH + tid];
        sNq[tid] = rp[0 * CH + tid] + rp[rstr + 0 * CH + tid] + rp[2 * rstr + 0 * CH + tid];
        sNk[tid] = rp[1 * CH + tid] + rp[rstr + 1 * CH + tid] + rp[2 * rstr + 1 * CH + tid];
        sP1[tid] = rp[2 * CH + tid] + rp[rstr + 2 * CH + tid] + rp[2 * rstr + 2 * CH + tid];
        sP2[tid] = rp[3 * CH + tid] + rp[rstr + 3 * CH + tid] + rp[2 * rstr + 3 * CH + tid];
    }
    for (int i = tid; i < CH * 128; i += 256) {
        int d = i >> 7, kk = i & 127;
        sW[d * 130 + kk] = w3h[d * Cc + k0 + kk];
    }
    __syncthreads();

    const float tH = temp[h];
#pragma unroll
    for (int e = 0; e < 9; e++) {
        int idx = tid + 256 * e;
        int c = idx / CH, d = idx - c * CH;
        float g = Gp[idx] + Gp[gstr + idx] + Gp[2 * gstr + idx];
        float b1c = sB1[c], b2d = sB2[d];
        float nq = sqrtf(fmaxf(sNq[c] + 2.f * b1c * sP1[c] + 4096.f * b1c * b1c, 0.f));
        float nk = sqrtf(fmaxf(sNk[d] + 2.f * b2d * sP2[d] + 4096.f * b2d * b2d, 0.f));
        g = g + b1c * sP2[d] + b2d * sP1[c] + 4096.f * b1c * b2d;
        sAa[c * 49 + d] = g / (fmaxf(nq, 1e-12f) * fmaxf(nk, 1e-12f)) * tH;
    }
    __syncthreads();

    for (int c = warp * 6; c < warp * 6 + 6; c++) {
        float a0 = sAa[c * 49 + lane];
        float a1 = (lane < 16) ? sAa[c * 49 + 32 + lane] : -3.402823466e38f;
        float m = fmaxf(a0, a1);
#pragma unroll
        for (int o = 16; o; o >>= 1) m = fmaxf(m, __shfl_xor_sync(0xffffffffu, m, o));
        float e0 = __expf(a0 - m);
        float e1 = (lane < 16) ? __expf(a1 - m) : 0.f;
        float s = e0 + e1;
#pragma unroll
        for (int o = 16; o; o >>= 1) s += __shfl_xor_sync(0xffffffffu, s, o);
        float inv = 1.f / s;
        sAa[c * 49 + lane] = e0 * inv;
        if (lane < 16) sAa[c * 49 + 32 + lane] = e1 * inv;
    }
    __syncthreads();

    if (kt == 0 && tid < CH) {
        float s = sB3[tid];
#pragma unroll 8
        for (int d = 0; d < CH; d++) s += sAa[tid * 49 + d] * sB3[d];
        g_mb[b * Cc + h * CH + tid] = s;
    }

    const int kkl = tid & 127, half = tid >> 7;
    float w[CH];
#pragma unroll 12
    for (int d = 0; d < CH; d++) w[d] = sW[d * 130 + kkl];

    __half* Mrow = g_Mh + (size_t)b * Cc * Cc + (size_t)(h * CH) * Cc + k0 + kkl;
    for (int c = half * 24; c < half * 24 + 24; c++) {
        float s = w[0] * sAa[c * 49 + 0] + sW[c * 130 + kkl];
#pragma unroll 12
        for (int d = 1; d < CH; d++) s += sAa[c * 49 + d] * w[d];
        if (h * CH + c == k0 + kkl) s += 1.f;
        Mrow[(size_t)c * Cc] = __float2half_rn(s);
    }
}

// ---------------------------------------------------------------------------
extern "C" void kernel_launch(void* const* d_in, const int* in_sizes, int n_in,
                              void* d_out, int out_size)
{
    (void)in_sizes; (void)n_in; (void)out_size;
    const float* x    = (const float*)d_in[0];
    const float* w1   = (const float*)d_in[1];
    const float* b1   = (const float*)d_in[2];
    const float* w2   = (const float*)d_in[3];
    const float* b2   = (const float*)d_in[4];
    const float* w3   = (const float*)d_in[5];
    const float* b3   = (const float*)d_in[6];
    const float* temp = (const float*)d_in[7];
    float* out = (float*)d_out;

    cudaFuncSetAttribute(gemm_S,   cudaFuncAttributeMaxDynamicSharedMemorySize, DSMEM_S);
    cudaFuncSetAttribute(gemm_U,   cudaFuncAttributeMaxDynamicSharedMemorySize, DSMEM_S);
    cudaFuncSetAttribute(gemm_out, cudaFuncAttributeMaxDynamicSharedMemorySize, DSMEM_O);
    cudaFuncSetAttribute(k_attn1,  cudaFuncAttributeMaxDynamicSharedMemorySize, ATTN1_SM);

    k_convert<<<Bb * Cc, 256>>>(x);
    k_convW<<<dim3(WSZ / 1024, 2), 256>>>(w1, w2);

    gemm_S<<<dim3(6, 3, Bb), 256, DSMEM_S>>>();
    k_Sreduce<<<dim3(16, 6, Bb), 256>>>();

    gemm_U<<<dim3(6, 3, Bb), 256, DSMEM_S>>>();

    k_attn1<<<dim3(3, HEADS, Bb), 256, ATTN1_SM>>>(w1, w2);
    k_foldM<<<dim3(3, HEADS, Bb), 256>>>(w3, b1, b2, b3, temp);

    gemm_out<<<dim3(3, 32, Bb), 256, DSMEM_O>>>(out);
}

// round 16
// speedup vs baseline: 1.1939x; 1.0170x over previous
#include <cuda_runtime.h>
#include <cuda_fp16.h>
#include <math.h>
#include <stdint.h>

#define Bb 16
#define Cc 384
#define Nn 4096
#define HEADS 8
#define CH 48
#define SSZ (Bb*Cc*Cc)
#define WSZ (Cc*Cc)

// ---------------- scratch (device globals; allocation-free) ----------------
__device__ __half g_Sh[SSZ];                // S fp16
__device__ __half g_Mh[SSZ];                // folded (A+I)W3 + I (fp16)
__device__ __half g_Xh[(size_t)Bb*Cc*Nn];   // x fp16 [b][c][n]
__device__ __half g_W1h[WSZ], g_W2h[WSZ];   // weights fp16
__device__ float g_U1[SSZ], g_U2[SSZ];
__device__ float g_Sp[3*Bb*6*16384];        // split-K partial S tiles
__device__ float g_sx[Bb*Cc];               // row sums
__device__ float g_mb[Bb*Cc];
__device__ float g_Gp[3*Bb*HEADS*CH*CH];    // split-K partial Gqk
__device__ float g_rp[3*Bb*HEADS*4*CH];     // split-K partial row reductions

// ---------------- PTX helpers (sm_80-class; no 'a'-gated features) ---------
__device__ __forceinline__ uint32_t smem_u32(const void* p) {
    uint32_t a;
    asm("{ .reg .u64 t; cvta.to.shared.u64 t, %1; cvt.u32.u64 %0, t; }"
        : "=r"(a) : "l"(p));
    return a;
}
__device__ __forceinline__ void ldsm4(uint32_t* r, uint32_t addr) {
    asm volatile("ldmatrix.sync.aligned.m8n8.x4.shared.b16 {%0,%1,%2,%3}, [%4];"
                 : "=r"(r[0]), "=r"(r[1]), "=r"(r[2]), "=r"(r[3]) : "r"(addr));
}
__device__ __forceinline__ void ldsm4t(uint32_t* r, uint32_t addr) {
    asm volatile("ldmatrix.sync.aligned.m8n8.x4.trans.shared.b16 {%0,%1,%2,%3}, [%4];"
                 : "=r"(r[0]), "=r"(r[1]), "=r"(r[2]), "=r"(r[3]) : "r"(addr));
}
__device__ __forceinline__ void mma16816(float* c, const uint32_t* a, const uint32_t* b) {
    asm volatile(
        "mma.sync.aligned.m16n8k16.row.col.f32.f16.f16.f32 "
        "{%0,%1,%2,%3}, {%4,%5,%6,%7}, {%8,%9}, {%0,%1,%2,%3};"
        : "+f"(c[0]), "+f"(c[1]), "+f"(c[2]), "+f"(c[3])
        : "r"(a[0]), "r"(a[1]), "r"(a[2]), "r"(a[3]), "r"(b[0]), "r"(b[1]));
}
#define CP_ASYNC16(dst, src) \
    asm volatile("cp.async.cg.shared.global [%0], [%1], 16;" \
                 :: "r"(dst), "l"(__cvta_generic_to_global(src)))
#define CP_COMMIT() asm volatile("cp.async.commit_group;" ::: "memory")
#define CP_WAIT0()  asm volatile("cp.async.wait_group 0;" ::: "memory")
#define CP_WAIT1()  asm volatile("cp.async.wait_group 1;" ::: "memory")

// smem geometry
#define SROW80    80
#define ATILE     10240
#define STAGE_S1  20480     // Ah, Bh (1-pass NT); 3 stages
#define DSMEM_S   61440     // 3 stages; epilogue 64x132 fp32 fits -> 2 blk/SM
#define BPITCH    272
#define BTILE32   8704      // 32 * 272
#define STAGE_O32 18944     // ATILE + BTILE32; 3 stages
#define DSMEM_O   56832     // 3 stages -> still 2 blk/SM
#define ATTN1_SM  49920     // 2 * 48 * 130 * 4

// ---------------------------------------------------------------------------
// compute bodies (warp tile 32x64; acc[2][8][4])
// ---------------------------------------------------------------------------
__device__ __forceinline__ void compute_nt1(uint32_t smb, int wm, int wn, int lane,
                                            float acc[2][8][4]) {
    const int grp = lane >> 3, lr = lane & 7;
#pragma unroll
    for (int ks = 0; ks < 2; ks++) {
        const int kc = ks * 16;
        uint32_t ah[2][4];
#pragma unroll
        for (int ti = 0; ti < 2; ti++) {
            int row = wm * 32 + ti * 16 + lr + (grp & 1) * 8;
            int col = kc + (grp >> 1) * 8;
            ldsm4(ah[ti], smb + row * SROW80 + col * 2);
        }
#pragma unroll
        for (int half = 0; half < 2; half++) {
            uint32_t bhf[4][2];
#pragma unroll
            for (int p = 0; p < 2; p++) {
                int nrow = wn * 64 + half * 32 + p * 16 + (grp >> 1) * 8 + lr;
                int col = kc + (grp & 1) * 8;
                uint32_t r4[4];
                ldsm4(r4, smb + ATILE + nrow * SROW80 + col * 2);
                bhf[2*p][0] = r4[0]; bhf[2*p][1] = r4[1];
                bhf[2*p+1][0] = r4[2]; bhf[2*p+1][1] = r4[3];
            }
#pragma unroll
            for (int ti = 0; ti < 2; ti++)
#pragma unroll
                for (int tj = 0; tj < 4; tj++)
                    mma16816(acc[ti][half * 4 + tj], ah[ti], bhf[tj]);
        }
    }
}

// BK=32 trans-B compute
__device__ __forceinline__ void compute_o32(uint32_t smbA, uint32_t smbB,
                                            int wm, int wn, int lane,
                                            float acc[2][8][4]) {
    const int grp = lane >> 3, lr = lane & 7;
#pragma unroll
    for (int ks = 0; ks < 2; ks++) {
        const int kc = ks * 16;
        uint32_t ah[2][4];
#pragma unroll
        for (int ti = 0; ti < 2; ti++) {
            int row = wm * 32 + ti * 16 + lr + (grp & 1) * 8;
            int col = kc + (grp >> 1) * 8;
            ldsm4(ah[ti], smbA + row * SROW80 + col * 2);
        }
#pragma unroll
        for (int half = 0; half < 2; half++) {
            uint32_t bhf[4][2];
#pragma unroll
            for (int p = 0; p < 2; p++) {
                int krow = kc + ((lane >> 3) & 1) * 8 + (lane & 7);
                int ncol = wn * 64 + half * 32 + p * 16 + (lane >> 4) * 8;
                uint32_t r4[4];
                ldsm4t(r4, smbB + krow * BPITCH + ncol * 2);
                bhf[2*p][0] = r4[0]; bhf[2*p][1] = r4[1];
                bhf[2*p+1][0] = r4[2]; bhf[2*p+1][1] = r4[3];
            }
#pragma unroll
            for (int ti = 0; ti < 2; ti++)
#pragma unroll
                for (int tj = 0; tj < 4; tj++)
                    mma16816(acc[ti][half * 4 + tj], ah[ti], bhf[tj]);
        }
    }
}

// ---------------------------------------------------------------------------
// k_convert: x -> g_Xh (fp16) + g_sx (row sums). grid (Bb*Cc), 256 thr.
// ---------------------------------------------------------------------------
__global__ void __launch_bounds__(256) k_convert(const float* __restrict__ x) {
    const int row = blockIdx.x;
    const float4* xr = (const float4*)(x + (size_t)row * Nn);
    __half* xo = g_Xh + (size_t)row * Nn;
    float s = 0.f;
#pragma unroll
    for (int j = 0; j < 4; j++) {
        int idx = threadIdx.x + 256 * j;
        float4 v = xr[idx];
        s += (v.x + v.y) + (v.z + v.w);
        __half2 h01 = __floats2half2_rn(v.x, v.y);
        __half2 h23 = __floats2half2_rn(v.z, v.w);
        uint2 hh;
        hh.x = *(uint32_t*)&h01; hh.y = *(uint32_t*)&h23;
        *(uint2*)(xo + idx * 4) = hh;
    }
    __shared__ float red[256];
    red[threadIdx.x] = s;
    __syncthreads();
    for (int o = 128; o; o >>= 1) {
        if (threadIdx.x < o) red[threadIdx.x] += red[threadIdx.x + o];
        __syncthreads();
    }
    if (threadIdx.x == 0) g_sx[row] = red[0];
}

// k_convW: w1,w2 -> fp16. grid (WSZ/1024, 2), 256 thr.
__global__ void __launch_bounds__(256) k_convW(const float* __restrict__ w1,
                                               const float* __restrict__ w2) {
    const float* src = blockIdx.y ? w2 : w1;
    __half* dst = blockIdx.y ? g_W2h : g_W1h;
    int base = blockIdx.x * 1024 + threadIdx.x * 4;
    float4 v = *(const float4*)(src + base);
    __half2 h01 = __floats2half2_rn(v.x, v.y);
    __half2 h23 = __floats2half2_rn(v.z, v.w);
    uint2 hh;
    hh.x = *(uint32_t*)&h01; hh.y = *(uint32_t*)&h23;
    *(uint2*)(dst + base) = hh;
}

// ---------------------------------------------------------------------------
// S GEMM, triangle + split-K=3, 1-pass, cp.async 3-stage, fp16 in.
// Epilogue in two 64-row passes (smem 61440 -> 2 blocks/SM).
// grid (6 pairs, 3 kz, 16 batch)
// ---------------------------------------------------------------------------
__global__ void __launch_bounds__(256) gemm_S() {
    extern __shared__ char dsm[];
    const int pxl[6] = {0,0,0,1,1,2}, pyl[6] = {0,1,2,1,2,2};
    const int tid = threadIdx.x, lane = tid & 31, wid = tid >> 5;
    const int wm = wid & 3, wn = wid >> 2;
    const int pair = blockIdx.x, kz = blockIdx.y, bz = blockIdx.z;
    const int bx = pxl[pair], by = pyl[pair];
    const int c0 = (kz == 0) ? 0 : (kz == 1 ? 43 : 86);
    const int c1 = (kz == 0) ? 43 : (kz == 1 ? 86 : 128);
    const int nch = c1 - c0;
    const uint32_t smb = smem_u32(dsm);

    const __half* Ax = g_Xh + ((size_t)bz * Cc + bx * 128) * Nn + c0 * 32;
    const __half* Bx = g_Xh + ((size_t)bz * Cc + by * 128) * Nn + c0 * 32;

    int rw[2], qq[2];
#pragma unroll
    for (int j = 0; j < 2; j++) { int u = tid + 256 * j; rw[j] = u >> 2; qq[j] = u & 3; }

    float acc[2][8][4];
#pragma unroll
    for (int i = 0; i < 2; i++)
#pragma unroll
        for (int j = 0; j < 8; j++)
#pragma unroll
            for (int q = 0; q < 4; q++) acc[i][j][q] = 0.f;

#define ISSUE_S(chunk, stage) do { \
    uint32_t _b = smb + (stage) * STAGE_S1; \
    int _k = (chunk) * 32; \
    _Pragma("unroll") \
    for (int _j = 0; _j < 2; _j++) { \
        CP_ASYNC16(_b + rw[_j] * SROW80 + qq[_j] * 16, \
                   Ax + (size_t)rw[_j] * Nn + _k + qq[_j] * 8); \
        CP_ASYNC16(_b + ATILE + rw[_j] * SROW80 + qq[_j] * 16, \
                   Bx + (size_t)rw[_j] * Nn + _k + qq[_j] * 8); \
    } } while (0)

    ISSUE_S(0, 0); CP_COMMIT();
    ISSUE_S(1, 1); CP_COMMIT();

    int st = 0;
    for (int i = 0; i < nch; i++) {
        if (i == nch - 1) CP_WAIT0(); else CP_WAIT1();
        __syncthreads();
        if (i + 2 < nch) {
            int s2 = st + 2; if (s2 >= 3) s2 -= 3;
            ISSUE_S(i + 2, s2); CP_COMMIT();
        }
        compute_nt1(smb + st * STAGE_S1, wm, wn, lane, acc);
        if (++st == 3) st = 0;
    }
#undef ISSUE_S

    // epilogue: two 64-row passes through smem (fits 61440 budget)
    float* sC = (float*)dsm;
    float* outp = g_Sp + (((size_t)kz * Bb + bz) * 6 + pair) * 16384;
#pragma unroll
    for (int hp = 0; hp < 2; hp++) {
        __syncthreads();
        if ((wm >> 1) == hp) {
            const int lrow = (wm & 1) * 32;
#pragma unroll
            for (int ti = 0; ti < 2; ti++)
#pragma unroll
                for (int j = 0; j < 8; j++) {
                    int row0 = lrow + ti * 16 + (lane >> 2);
                    int col  = wn * 64 + j * 8 + (lane & 3) * 2;
                    *(float2*)(sC + row0 * 132 + col)       = make_float2(acc[ti][j][0], acc[ti][j][1]);
                    *(float2*)(sC + (row0 + 8) * 132 + col) = make_float2(acc[ti][j][2], acc[ti][j][3]);
                }
        }
        __syncthreads();
        const int row = tid >> 2, quad = tid & 3;   // 64 rows x 4 quarters
        const float* src = sC + row * 132 + quad * 32;
        float* dst = outp + (hp * 64 + row) * 128 + quad * 32;
#pragma unroll
        for (int j = 0; j < 32; j += 4)
            *(float4*)(dst + j) = *(const float4*)(src + j);
    }
}

// ---------------------------------------------------------------------------
// S reduce: sum 3 partials -> fp16 Sh (tile + transpose).
// grid (16 subtiles, 6 pairs, 16 batch)
// ---------------------------------------------------------------------------
__global__ void __launch_bounds__(256) k_Sreduce() {
    __shared__ float t[32][33];
    const int pxl[6] = {0,0,0,1,1,2}, pyl[6] = {0,1,2,1,2,2};
    const int sub = blockIdx.x, pair = blockIdx.y, bz = blockIdx.z;
    const int px = pxl[pair], py = pyl[pair];
    const int si = sub >> 2, sj = sub & 3;
    const int cc = threadIdx.x & 31, rb = threadIdx.x >> 5;

    const size_t stride = (size_t)Bb * 6 * 16384;
    const float* p0 = g_Sp + ((size_t)bz * 6 + pair) * 16384;
    const float* p1 = p0 + stride;
    const float* p2 = p0 + 2 * stride;
    const size_t gb = (size_t)bz * Cc * Cc;

#pragma unroll
    for (int r = 0; r < 4; r++) {
        int rr = rb + r * 8;
        int li = (si * 32 + rr) * 128 + sj * 32 + cc;
        float s = p0[li] + p1[li] + p2[li];
        t[rr][cc] = s;
        size_t o = gb + (size_t)(px * 128 + si * 32 + rr) * Cc + py * 128 + sj * 32 + cc;
        g_Sh[o] = __float2half_rn(s);
    }
    if (px == py) return;
    __syncthreads();
#pragma unroll
    for (int r = 0; r < 4; r++) {
        int rr = rb + r * 8;
        float s = t[cc][rr];
        size_t o = gb + (size_t)(py * 128 + sj * 32 + rr) * Cc + px * 128 + si * 32 + cc;
        g_Sh[o] = __float2half_rn(s);
    }
}

// ---------------------------------------------------------------------------
// U GEMM (fused U1+U2), 1-pass, cp.async 3-stage, fp16 W. grid (6,3,16).
// ---------------------------------------------------------------------------
__global__ void __launch_bounds__(256) gemm_U() {
    extern __shared__ char dsm[];
    const int tid = threadIdx.x, lane = tid & 31, wid = tid >> 5;
    const int wm = wid & 3, wn = wid >> 2;
    const int sel = blockIdx.x >= 3;
    const int bx = blockIdx.x - (sel ? 3 : 0);
    const int by = blockIdx.y, bz = blockIdx.z;
    const uint32_t smb = smem_u32(dsm);

    const __half* Ax = (sel ? g_W2h : g_W1h) + (size_t)bx * 128 * Cc;
    const __half* Bx = g_Sh + (size_t)bz * Cc * Cc + (size_t)by * 128 * Cc;
    float* Cf = sel ? g_U2 : g_U1;

    int rw[2], qq[2];
#pragma unroll
    for (int j = 0; j < 2; j++) { int u = tid + 256 * j; rw[j] = u >> 2; qq[j] = u & 3; }

    float acc[2][8][4];
#pragma unroll
    for (int i = 0; i < 2; i++)
#pragma unroll
        for (int j = 0; j < 8; j++)
#pragma unroll
            for (int q = 0; q < 4; q++) acc[i][j][q] = 0.f;

#define ISSUE_U(chunk, stage) do { \
    uint32_t _b = smb + (stage) * STAGE_S1; \
    int _k = (chunk) * 32; \
    _Pragma("unroll") \
    for (int _j = 0; _j < 2; _j++) { \
        CP_ASYNC16(_b + rw[_j] * SROW80 + qq[_j] * 16, \
                   Ax + (size_t)rw[_j] * Cc + _k + qq[_j] * 8); \
        CP_ASYNC16(_b + ATILE + rw[_j] * SROW80 + qq[_j] * 16, \
                   Bx + (size_t)rw[_j] * Cc + _k + qq[_j] * 8); \
    } } while (0)

    ISSUE_U(0, 0); CP_COMMIT();
    ISSUE_U(1, 1); CP_COMMIT();

    const int nch = Cc / 32;   // 12
    int st = 0;
    for (int i = 0; i < nch; i++) {
        if (i == nch - 1) CP_WAIT0(); else CP_WAIT1();
        __syncthreads();
        if (i + 2 < nch) {
            int s2 = st + 2; if (s2 >= 3) s2 -= 3;
            ISSUE_U(i + 2, s2); CP_COMMIT();
        }
        compute_nt1(smb + st * STAGE_S1, wm, wn, lane, acc);
        if (++st == 3) st = 0;
    }
#undef ISSUE_U

    // epilogue: two 64-row passes (smem 61440 budget)
    float* sC = (float*)dsm;
#pragma unroll
    for (int hp = 0; hp < 2; hp++) {
        __syncthreads();
        if ((wm >> 1) == hp) {
            const int lrow = (wm & 1) * 32;
#pragma unroll
            for (int ti = 0; ti < 2; ti++)
#pragma unroll
                for (int j = 0; j < 8; j++) {
                    int row0 = lrow + ti * 16 + (lane >> 2);
                    int col  = wn * 64 + j * 8 + (lane & 3) * 2;
                    *(float2*)(sC + row0 * 132 + col)       = make_float2(acc[ti][j][0], acc[ti][j][1]);
                    *(float2*)(sC + (row0 + 8) * 132 + col) = make_float2(acc[ti][j][2], acc[ti][j][3]);
                }
        }
        __syncthreads();
        const int row = tid >> 2, quad = tid & 3;
        const float* src = sC + row * 132 + quad * 32;
        size_t base = ((size_t)bz * Cc + bx * 128 + hp * 64 + row) * Cc + by * 128 + quad * 32;
#pragma unroll
        for (int j = 0; j < 32; j += 4)
            *(float4*)(Cf + base + j) = *(const float4*)(src + j);
    }
}

// ---------------------------------------------------------------------------
// out GEMM, 1-pass, BK=32, cp.async 3-stage, 2 blocks/SM (smem 56832):
// out = Mh Xh + mb. Epilogue in two 64-row passes. grid (3,32,16).
// ---------------------------------------------------------------------------
__global__ void __launch_bounds__(256) gemm_out(float* __restrict__ out)
{
    extern __shared__ char dsm[];
    const int tid = threadIdx.x, lane = tid & 31, wid = tid >> 5;
    const int wm = wid & 3, wn = wid >> 2;
    const int bx = blockIdx.x, by = blockIdx.y, bz = blockIdx.z;
    const uint32_t smb = smem_u32(dsm);

    const __half* pA = g_Mh + (size_t)bz * Cc * Cc + (size_t)bx * 128 * Cc;
    const __half* pB = g_Xh + (size_t)bz * Cc * Nn + by * 128;

    int arw[2], aq[2];
#pragma unroll
    for (int j = 0; j < 2; j++) { int u = tid + 256 * j; arw[j] = u >> 2; aq[j] = u & 3; }
    int brw[2], bq[2];
#pragma unroll
    for (int j = 0; j < 2; j++) { int u = tid + 256 * j; brw[j] = u >> 4; bq[j] = u & 15; }

    float acc[2][8][4];
#pragma unroll
    for (int i = 0; i < 2; i++)
#pragma unroll
        for (int j = 0; j < 8; j++)
#pragma unroll
            for (int q = 0; q < 4; q++) acc[i][j][q] = 0.f;

#define ISSUE_O(chunk, stage) do { \
    uint32_t _b = smb + (stage) * STAGE_O32; \
    int _k = (chunk) * 32; \
    _Pragma("unroll") \
    for (int _j = 0; _j < 2; _j++) { \
        CP_ASYNC16(_b + arw[_j] * SROW80 + aq[_j] * 16, \
                   pA + (size_t)arw[_j] * Cc + _k + aq[_j] * 8); \
        CP_ASYNC16(_b + ATILE + brw[_j] * BPITCH + bq[_j] * 16, \
                   pB + (size_t)(_k + brw[_j]) * Nn + bq[_j] * 8); \
    } } while (0)

    ISSUE_O(0, 0); CP_COMMIT();
    ISSUE_O(1, 1); CP_COMMIT();

    const int nch = Cc / 32;   // 12
    int st = 0;
    for (int i = 0; i < nch; i++) {
        if (i == nch - 1) CP_WAIT0(); else CP_WAIT1();
        __syncthreads();
        if (i + 2 < nch) {
            int s2 = st + 2; if (s2 >= 3) s2 -= 3;
            ISSUE_O(i + 2, s2); CP_COMMIT();
        }
        uint32_t sb = smb + st * STAGE_O32;
        compute_o32(sb, sb + ATILE, wm, wn, lane, acc);
        if (++st == 3) st = 0;
    }
#undef ISSUE_O

    // epilogue: two 64-row passes through smem
    float* sC = (float*)dsm;
#pragma unroll
    for (int hp = 0; hp < 2; hp++) {
        __syncthreads();
        if ((wm >> 1) == hp) {
            const int lrow = (wm & 1) * 32;
#pragma unroll
            for (int ti = 0; ti < 2; ti++)
#pragma unroll
                for (int j = 0; j < 8; j++) {
                    int row0 = lrow + ti * 16 + (lane >> 2);
                    int col  = wn * 64 + j * 8 + (lane & 3) * 2;
                    *(float2*)(sC + row0 * 132 + col)       = make_float2(acc[ti][j][0], acc[ti][j][1]);
                    *(float2*)(sC + (row0 + 8) * 132 + col) = make_float2(acc[ti][j][2], acc[ti][j][3]);
                }
        }
        __syncthreads();
        const int row = tid >> 2, quad = tid & 3;
        const float* src = sC + row * 132 + quad * 32;
        const int grow = bx * 128 + hp * 64 + row;
        float bias = g_mb[bz * Cc + grow];
        float* dst = out + ((size_t)bz * Cc + grow) * (size_t)Nn + by * 128 + quad * 32;
#pragma unroll
        for (int j = 0; j < 32; j += 4) {
            float4 v4 = *(const float4*)(src + j);
            *(float4*)(dst + j) = make_float4(v4.x + bias, v4.y + bias,
                                              v4.z + bias, v4.w + bias);
        }
    }
}

// ---------------------------------------------------------------------------
// k_attn1: split-K (3 x 128-wide) partial Gqk + row reductions.
// grid (3, HEADS, Bb).
// ---------------------------------------------------------------------------
__global__ void __launch_bounds__(256) k_attn1(
    const float* __restrict__ w1, const float* __restrict__ w2)
{
    extern __shared__ float satt[];       // sU[48*130], sW[48*130]
    float* sU = satt;
    float* sW = satt + CH * 130;

    const int kt = blockIdx.x, h = blockIdx.y, b = blockIdx.z;
    const int k0 = kt * 128;
    const int tid = threadIdx.x;
    const int warp = tid >> 5, lane = tid & 31;

    const float* U1  = &g_U1[(size_t)b * Cc * Cc + (size_t)h * CH * Cc];
    const float* U2  = &g_U2[(size_t)b * Cc * Cc + (size_t)h * CH * Cc];
    const float* w1h = w1 + (size_t)h * CH * Cc;
    const float* w2h = w2 + (size_t)h * CH * Cc;

    for (int i = tid; i < CH * 128; i += 256) {
        int c = i >> 7, kk = i & 127;
        sU[c * 130 + kk] = U1[c * Cc + k0 + kk];
        sW[c * 130 + kk] = w2h[c * Cc + k0 + kk];
    }
    __syncthreads();

    const int ci0 = (tid >> 4) * 3, di0 = (tid & 15) * 3;
    float acc[3][3];
#pragma unroll
    for (int i = 0; i < 3; i++)
#pragma unroll
        for (int j = 0; j < 3; j++) acc[i][j] = 0.f;
#pragma unroll 8
    for (int kk = 0; kk < 128; kk++) {
        float u[3], w[3];
#pragma unroll
        for (int i = 0; i < 3; i++) u[i] = sU[(ci0 + i) * 130 + kk];
#pragma unroll
        for (int j = 0; j < 3; j++) w[j] = sW[(di0 + j) * 130 + kk];
#pragma unroll
        for (int i = 0; i < 3; i++)
#pragma unroll
            for (int j = 0; j < 3; j++) acc[i][j] += u[i] * w[j];
    }
    float* Gp = g_Gp + (((size_t)kt * Bb + b) * HEADS + h) * (CH * CH);
#pragma unroll
    for (int i = 0; i < 3; i++)
#pragma unroll
        for (int j = 0; j < 3; j++)
            Gp[(ci0 + i) * CH + di0 + j] = acc[i][j];

    float* rp = g_rp + (((size_t)kt * Bb + b) * HEADS + h) * (4 * CH);
    for (int c = warp * 6; c < warp * 6 + 6; c++) {
        float aq = 0.f, ak = 0.f, p1 = 0.f, p2 = 0.f;
#pragma unroll
        for (int it = 0; it < 4; it++) {
            int k = k0 + lane + it * 32;
            float w1v = w1h[c * Cc + k];
            float w2v = w2h[c * Cc + k];
            aq += U1[c * Cc + k] * w1v;
            ak += U2[c * Cc + k] * w2v;
            float sv = g_sx[(size_t)b * Cc + k];
            p1 += w1v * sv;
            p2 += w2v * sv;
        }
#pragma unroll
        for (int o = 16; o; o >>= 1) {
            aq += __shfl_xor_sync(0xffffffffu, aq, o);
            ak += __shfl_xor_sync(0xffffffffu, ak, o);
            p1 += __shfl_xor_sync(0xffffffffu, p1, o);
            p2 += __shfl_xor_sync(0xffffffffu, p2, o);
        }
        if (lane == 0) {
            rp[0 * CH + c] = aq;
            rp[1 * CH + c] = ak;
            rp[2 * CH + c] = p1;
            rp[3 * CH + c] = p2;
        }
    }
}

// ---------------------------------------------------------------------------
// k_foldM: combine partials -> softmax A (redundant per kt), fold M k-slice,
// kt==0 writes mb. grid (3, HEADS, Bb).
// ---------------------------------------------------------------------------
__global__ void __launch_bounds__(256) k_foldM(
    const float* __restrict__ w3, const float* __restrict__ b1,
    const float* __restrict__ b2, const float* __restrict__ b3,
    const float* __restrict__ temp)
{
    __shared__ float sAa[CH * 49];
    __shared__ float sW[CH * 130];
    __shared__ float sNq[CH], sNk[CH], sP1[CH], sP2[CH];
    __shared__ float sB1[CH], sB2[CH], sB3[CH];

    const int kt = blockIdx.x, h = blockIdx.y, b = blockIdx.z;
    const int k0 = kt * 128;
    const int tid = threadIdx.x;
    const int warp = tid >> 5, lane = tid & 31;

    const size_t gstr = (size_t)Bb * HEADS * CH * CH;
    const size_t rstr = (size_t)Bb * HEADS * 4 * CH;
    const float* Gp = g_Gp + ((size_t)b * HEADS + h) * (CH * CH);
    const float* rp = g_rp + ((size_t)b * HEADS + h) * (4 * CH);
    const float* w3h = w3 + (size_t)h * CH * Cc;

    if (tid < CH) {
        sB1[tid] = b1[h * CH + tid];
        sB2[tid] = b2[h * CH + tid];
        sB3[tid] = b3[h * CH + tid];
        sNq[tid] = rp[0 * CH + tid] + rp[rstr + 0 * CH + tid] + rp[2 * rstr + 0 * CH + tid];
        sNk[tid] = rp[1 * CH + tid] + rp[rstr + 1 * CH + tid] + rp[2 * rstr + 1 * CH + tid];
        sP1[tid] = rp[2 * CH + tid] + rp[rstr + 2 * CH + tid] + rp[2 * rstr + 2 * CH + tid];
        sP2[tid] = rp[3 * CH + tid] + rp[rstr + 3 * CH + tid] + rp[2 * rstr + 3 * CH + tid];
    }
    for (int i = tid; i < CH * 128; i += 256) {
        int d = i >> 7, kk = i & 127;
        sW[d * 130 + kk] = w3h[d * Cc + k0 + kk];
    }
    __syncthreads();

    const float tH = temp[h];
#pragma unroll
    for (int e = 0; e < 9; e++) {
        int idx = tid + 256 * e;
        int c = idx / CH, d = idx - c * CH;
        float g = Gp[idx] + Gp[gstr + idx] + Gp[2 * gstr + idx];
        float b1c = sB1[c], b2d = sB2[d];
        float nq = sqrtf(fmaxf(sNq[c] + 2.f * b1c * sP1[c] + 4096.f * b1c * b1c, 0.f));
        float nk = sqrtf(fmaxf(sNk[d] + 2.f * b2d * sP2[d] + 4096.f * b2d * b2d, 0.f));
        g = g + b1c * sP2[d] + b2d * sP1[c] + 4096.f * b1c * b2d;
        sAa[c * 49 + d] = g / (fmaxf(nq, 1e-12f) * fmaxf(nk, 1e-12f)) * tH;
    }
    __syncthreads();

    for (int c = warp * 6; c < warp * 6 + 6; c++) {
        float a0 = sAa[c * 49 + lane];
        float a1 = (lane < 16) ? sAa[c * 49 + 32 + lane] : -3.402823466e38f;
        float m = fmaxf(a0, a1);
#pragma unroll
        for (int o = 16; o; o >>= 1) m = fmaxf(m, __shfl_xor_sync(0xffffffffu, m, o));
        float e0 = __expf(a0 - m);
        float e1 = (lane < 16) ? __expf(a1 - m) : 0.f;
        float s = e0 + e1;
#pragma unroll
        for (int o = 16; o; o >>= 1) s += __shfl_xor_sync(0xffffffffu, s, o);
        float inv = 1.f / s;
        sAa[c * 49 + lane] = e0 * inv;
        if (lane < 16) sAa[c * 49 + 32 + lane] = e1 * inv;
    }
    __syncthreads();

    if (kt == 0 && tid < CH) {
        float s = sB3[tid];
#pragma unroll 8
        for (int d = 0; d < CH; d++) s += sAa[tid * 49 + d] * sB3[d];
        g_mb[b * Cc + h * CH + tid] = s;
    }

    const int kkl = tid & 127, half = tid >> 7;
    float w[CH];
#pragma unroll 12
    for (int d = 0; d < CH; d++) w[d] = sW[d * 130 + kkl];

    __half* Mrow = g_Mh + (size_t)b * Cc * Cc + (size_t)(h * CH) * Cc + k0 + kkl;
    for (int c = half * 24; c < half * 24 + 24; c++) {
        float s = w[0] * sAa[c * 49 + 0] + sW[c * 130 + kkl];
#pragma unroll 12
        for (int d = 1; d < CH; d++) s += sAa[c * 49 + d] * w[d];
        if (h * CH + c == k0 + kkl) s += 1.f;
        Mrow[(size_t)c * Cc] = __float2half_rn(s);
    }
}

// ---------------------------------------------------------------------------
extern "C" void kernel_launch(void* const* d_in, const int* in_sizes, int n_in,
                              void* d_out, int out_size)
{
    (void)in_sizes; (void)n_in; (void)out_size;
    const float* x    = (const float*)d_in[0];
    const float* w1   = (const float*)d_in[1];
    const float* b1   = (const float*)d_in[2];
    const float* w2   = (const float*)d_in[3];
    const float* b2   = (const float*)d_in[4];
    const float* w3   = (const float*)d_in[5];
    const float* b3   = (const float*)d_in[6];
    const float* temp = (const float*)d_in[7];
    float* out = (float*)d_out;

    cudaFuncSetAttribute(gemm_S,   cudaFuncAttributeMaxDynamicSharedMemorySize, DSMEM_S);
    cudaFuncSetAttribute(gemm_U,   cudaFuncAttributeMaxDynamicSharedMemorySize, DSMEM_S);
    cudaFuncSetAttribute(gemm_out, cudaFuncAttributeMaxDynamicSharedMemorySize, DSMEM_O);
    cudaFuncSetAttribute(k_attn1,  cudaFuncAttributeMaxDynamicSharedMemorySize, ATTN1_SM);

    k_convert<<<Bb * Cc, 256>>>(x);
    k_convW<<<dim3(WSZ / 1024, 2), 256>>>(w1, w2);

    gemm_S<<<dim3(6, 3, Bb), 256, DSMEM_S>>>();
    k_Sreduce<<<dim3(16, 6, Bb), 256>>>();

    gemm_U<<<dim3(6, 3, Bb), 256, DSMEM_S>>>();

    k_attn1<<<dim3(3, HEADS, Bb), 256, ATTN1_SM>>>(w1, w2);
    k_foldM<<<dim3(3, HEADS, Bb), 256>>>(w3, b1, b2, b3, temp);

    gemm_out<<<dim3(3, 32, Bb), 256, DSMEM_O>>>(out);
}

// round 17
// speedup vs baseline: 1.2076x; 1.0114x over previous
#include <cuda_runtime.h>
#include <cuda_fp16.h>
#include <math.h>
#include <stdint.h>

#define Bb 16
#define Cc 384
#define Nn 4096
#define HEADS 8
#define CH 48
#define SSZ (Bb*Cc*Cc)
#define WSZ (Cc*Cc)

// ---------------- scratch (device globals; allocation-free) ----------------
__device__ __half g_Sh[SSZ];                // S fp16
__device__ __half g_Mh[SSZ];                // folded (A+I)W3 + I (fp16)
__device__ __half g_Xh[(size_t)Bb*Cc*Nn];   // x fp16 [b][c][n]
__device__ __half g_W1h[WSZ], g_W2h[WSZ];   // weights fp16
__device__ float g_U1[SSZ], g_U2[SSZ];
__device__ __half g_Sp[3*Bb*6*16384];       // split-K partial S tiles (fp16)
__device__ float g_sx[Bb*Cc];               // row sums
__device__ float g_mb[Bb*Cc];
__device__ float g_Gp[3*Bb*HEADS*CH*CH];    // split-K partial Gqk
__device__ float g_rp[3*Bb*HEADS*4*CH];     // split-K partial row reductions

// ---------------- PTX helpers (sm_80-class; no 'a'-gated features) ---------
__device__ __forceinline__ uint32_t smem_u32(const void* p) {
    uint32_t a;
    asm("{ .reg .u64 t; cvta.to.shared.u64 t, %1; cvt.u32.u64 %0, t; }"
        : "=r"(a) : "l"(p));
    return a;
}
__device__ __forceinline__ void ldsm4(uint32_t* r, uint32_t addr) {
    asm volatile("ldmatrix.sync.aligned.m8n8.x4.shared.b16 {%0,%1,%2,%3}, [%4];"
                 : "=r"(r[0]), "=r"(r[1]), "=r"(r[2]), "=r"(r[3]) : "r"(addr));
}
__device__ __forceinline__ void ldsm4t(uint32_t* r, uint32_t addr) {
    asm volatile("ldmatrix.sync.aligned.m8n8.x4.trans.shared.b16 {%0,%1,%2,%3}, [%4];"
                 : "=r"(r[0]), "=r"(r[1]), "=r"(r[2]), "=r"(r[3]) : "r"(addr));
}
__device__ __forceinline__ void mma16816(float* c, const uint32_t* a, const uint32_t* b) {
    asm volatile(
        "mma.sync.aligned.m16n8k16.row.col.f32.f16.f16.f32 "
        "{%0,%1,%2,%3}, {%4,%5,%6,%7}, {%8,%9}, {%0,%1,%2,%3};"
        : "+f"(c[0]), "+f"(c[1]), "+f"(c[2]), "+f"(c[3])
        : "r"(a[0]), "r"(a[1]), "r"(a[2]), "r"(a[3]), "r"(b[0]), "r"(b[1]));
}
#define CP_ASYNC16(dst, src) \
    asm volatile("cp.async.cg.shared.global [%0], [%1], 16;" \
                 :: "r"(dst), "l"(__cvta_generic_to_global(src)))
#define CP_COMMIT() asm volatile("cp.async.commit_group;" ::: "memory")
#define CP_WAIT0()  asm volatile("cp.async.wait_group 0;" ::: "memory")
#define CP_WAIT1()  asm volatile("cp.async.wait_group 1;" ::: "memory")

// smem geometry
#define SROW80    80
#define ATILE     10240
#define STAGE_S1  20480     // Ah, Bh (1-pass NT); 3 stages
#define DSMEM_S   61440     // 3 stages; 2 blk/SM
#define BPITCH    272
#define BTILE32   8704
#define STAGE_O32 18944     // 3 stages
#define DSMEM_O   56832     // 2 blk/SM
#define ATTN1_SM  49920

// ---------------------------------------------------------------------------
// compute bodies (warp tile 32x64; acc[2][8][4])
// ---------------------------------------------------------------------------
__device__ __forceinline__ void compute_nt1(uint32_t smb, int wm, int wn, int lane,
                                            float acc[2][8][4]) {
    const int grp = lane >> 3, lr = lane & 7;
#pragma unroll
    for (int ks = 0; ks < 2; ks++) {
        const int kc = ks * 16;
        uint32_t ah[2][4];
#pragma unroll
        for (int ti = 0; ti < 2; ti++) {
            int row = wm * 32 + ti * 16 + lr + (grp & 1) * 8;
            int col = kc + (grp >> 1) * 8;
            ldsm4(ah[ti], smb + row * SROW80 + col * 2);
        }
#pragma unroll
        for (int half = 0; half < 2; half++) {
            uint32_t bhf[4][2];
#pragma unroll
            for (int p = 0; p < 2; p++) {
                int nrow = wn * 64 + half * 32 + p * 16 + (grp >> 1) * 8 + lr;
                int col = kc + (grp & 1) * 8;
                uint32_t r4[4];
                ldsm4(r4, smb + ATILE + nrow * SROW80 + col * 2);
                bhf[2*p][0] = r4[0]; bhf[2*p][1] = r4[1];
                bhf[2*p+1][0] = r4[2]; bhf[2*p+1][1] = r4[3];
            }
#pragma unroll
            for (int ti = 0; ti < 2; ti++)
#pragma unroll
                for (int tj = 0; tj < 4; tj++)
                    mma16816(acc[ti][half * 4 + tj], ah[ti], bhf[tj]);
        }
    }
}

__device__ __forceinline__ void compute_o32(uint32_t smbA, uint32_t smbB,
                                            int wm, int wn, int lane,
                                            float acc[2][8][4]) {
    const int grp = lane >> 3, lr = lane & 7;
#pragma unroll
    for (int ks = 0; ks < 2; ks++) {
        const int kc = ks * 16;
        uint32_t ah[2][4];
#pragma unroll
        for (int ti = 0; ti < 2; ti++) {
            int row = wm * 32 + ti * 16 + lr + (grp & 1) * 8;
            int col = kc + (grp >> 1) * 8;
            ldsm4(ah[ti], smbA + row * SROW80 + col * 2);
        }
#pragma unroll
        for (int half = 0; half < 2; half++) {
            uint32_t bhf[4][2];
#pragma unroll
            for (int p = 0; p < 2; p++) {
                int krow = kc + ((lane >> 3) & 1) * 8 + (lane & 7);
                int ncol = wn * 64 + half * 32 + p * 16 + (lane >> 4) * 8;
                uint32_t r4[4];
                ldsm4t(r4, smbB + krow * BPITCH + ncol * 2);
                bhf[2*p][0] = r4[0]; bhf[2*p][1] = r4[1];
                bhf[2*p+1][0] = r4[2]; bhf[2*p+1][1] = r4[3];
            }
#pragma unroll
            for (int ti = 0; ti < 2; ti++)
#pragma unroll
                for (int tj = 0; tj < 4; tj++)
                    mma16816(acc[ti][half * 4 + tj], ah[ti], bhf[tj]);
        }
    }
}

// ---------------------------------------------------------------------------
// k_convert: x -> g_Xh (fp16) + g_sx (row sums). grid (Bb*Cc), 256 thr.
// ---------------------------------------------------------------------------
__global__ void __launch_bounds__(256) k_convert(const float* __restrict__ x) {
    const int row = blockIdx.x;
    const float4* xr = (const float4*)(x + (size_t)row * Nn);
    __half* xo = g_Xh + (size_t)row * Nn;
    float s = 0.f;
#pragma unroll
    for (int j = 0; j < 4; j++) {
        int idx = threadIdx.x + 256 * j;
        float4 v = xr[idx];
        s += (v.x + v.y) + (v.z + v.w);
        __half2 h01 = __floats2half2_rn(v.x, v.y);
        __half2 h23 = __floats2half2_rn(v.z, v.w);
        uint2 hh;
        hh.x = *(uint32_t*)&h01; hh.y = *(uint32_t*)&h23;
        *(uint2*)(xo + idx * 4) = hh;
    }
    __shared__ float red[256];
    red[threadIdx.x] = s;
    __syncthreads();
    for (int o = 128; o; o >>= 1) {
        if (threadIdx.x < o) red[threadIdx.x] += red[threadIdx.x + o];
        __syncthreads();
    }
    if (threadIdx.x == 0) g_sx[row] = red[0];
}

// k_convW: w1,w2 -> fp16. grid (WSZ/1024, 2), 256 thr.
__global__ void __launch_bounds__(256) k_convW(const float* __restrict__ w1,
                                               const float* __restrict__ w2) {
    const float* src = blockIdx.y ? w2 : w1;
    __half* dst = blockIdx.y ? g_W2h : g_W1h;
    int base = blockIdx.x * 1024 + threadIdx.x * 4;
    float4 v = *(const float4*)(src + base);
    __half2 h01 = __floats2half2_rn(v.x, v.y);
    __half2 h23 = __floats2half2_rn(v.z, v.w);
    uint2 hh;
    hh.x = *(uint32_t*)&h01; hh.y = *(uint32_t*)&h23;
    *(uint2*)(dst + base) = hh;
}

// ---------------------------------------------------------------------------
// S GEMM, triangle + split-K=3, 1-pass, cp.async 3-stage, fp16 in/out.
// Epilogue in two 64-row passes; partials written fp16.
// grid (6 pairs, 3 kz, 16 batch)
// ---------------------------------------------------------------------------
__global__ void __launch_bounds__(256) gemm_S() {
    extern __shared__ char dsm[];
    const int pxl[6] = {0,0,0,1,1,2}, pyl[6] = {0,1,2,1,2,2};
    const int tid = threadIdx.x, lane = tid & 31, wid = tid >> 5;
    const int wm = wid & 3, wn = wid >> 2;
    const int pair = blockIdx.x, kz = blockIdx.y, bz = blockIdx.z;
    const int bx = pxl[pair], by = pyl[pair];
    const int c0 = (kz == 0) ? 0 : (kz == 1 ? 43 : 86);
    const int c1 = (kz == 0) ? 43 : (kz == 1 ? 86 : 128);
    const int nch = c1 - c0;
    const uint32_t smb = smem_u32(dsm);

    const __half* Ax = g_Xh + ((size_t)bz * Cc + bx * 128) * Nn + c0 * 32;
    const __half* Bx = g_Xh + ((size_t)bz * Cc + by * 128) * Nn + c0 * 32;

    int rw[2], qq[2];
#pragma unroll
    for (int j = 0; j < 2; j++) { int u = tid + 256 * j; rw[j] = u >> 2; qq[j] = u & 3; }

    float acc[2][8][4];
#pragma unroll
    for (int i = 0; i < 2; i++)
#pragma unroll
        for (int j = 0; j < 8; j++)
#pragma unroll
            for (int q = 0; q < 4; q++) acc[i][j][q] = 0.f;

#define ISSUE_S(chunk, stage) do { \
    uint32_t _b = smb + (stage) * STAGE_S1; \
    int _k = (chunk) * 32; \
    _Pragma("unroll") \
    for (int _j = 0; _j < 2; _j++) { \
        CP_ASYNC16(_b + rw[_j] * SROW80 + qq[_j] * 16, \
                   Ax + (size_t)rw[_j] * Nn + _k + qq[_j] * 8); \
        CP_ASYNC16(_b + ATILE + rw[_j] * SROW80 + qq[_j] * 16, \
                   Bx + (size_t)rw[_j] * Nn + _k + qq[_j] * 8); \
    } } while (0)

    ISSUE_S(0, 0); CP_COMMIT();
    ISSUE_S(1, 1); CP_COMMIT();

    int st = 0;
    for (int i = 0; i < nch; i++) {
        if (i == nch - 1) CP_WAIT0(); else CP_WAIT1();
        __syncthreads();
        if (i + 2 < nch) {
            int s2 = st + 2; if (s2 >= 3) s2 -= 3;
            ISSUE_S(i + 2, s2); CP_COMMIT();
        }
        compute_nt1(smb + st * STAGE_S1, wm, wn, lane, acc);
        if (++st == 3) st = 0;
    }
#undef ISSUE_S

    // epilogue: two 64-row passes; convert to fp16 partials
    float* sC = (float*)dsm;
    __half* outp = g_Sp + (((size_t)kz * Bb + bz) * 6 + pair) * 16384;
#pragma unroll
    for (int hp = 0; hp < 2; hp++) {
        __syncthreads();
        if ((wm >> 1) == hp) {
            const int lrow = (wm & 1) * 32;
#pragma unroll
            for (int ti = 0; ti < 2; ti++)
#pragma unroll
                for (int j = 0; j < 8; j++) {
                    int row0 = lrow + ti * 16 + (lane >> 2);
                    int col  = wn * 64 + j * 8 + (lane & 3) * 2;
                    *(float2*)(sC + row0 * 132 + col)       = make_float2(acc[ti][j][0], acc[ti][j][1]);
                    *(float2*)(sC + (row0 + 8) * 132 + col) = make_float2(acc[ti][j][2], acc[ti][j][3]);
                }
        }
        __syncthreads();
        const int row = tid >> 2, quad = tid & 3;
        const float* src = sC + row * 132 + quad * 32;
        __half* dst = outp + (hp * 64 + row) * 128 + quad * 32;
#pragma unroll
        for (int g = 0; g < 4; g++) {
            uint4 v;
            __half2 p0 = __floats2half2_rn(src[g*8+0], src[g*8+1]);
            __half2 p1 = __floats2half2_rn(src[g*8+2], src[g*8+3]);
            __half2 p2 = __floats2half2_rn(src[g*8+4], src[g*8+5]);
            __half2 p3 = __floats2half2_rn(src[g*8+6], src[g*8+7]);
            v.x = *(uint32_t*)&p0; v.y = *(uint32_t*)&p1;
            v.z = *(uint32_t*)&p2; v.w = *(uint32_t*)&p3;
            *(uint4*)(dst + g * 8) = v;
        }
    }
}

// ---------------------------------------------------------------------------
// S reduce: sum 3 fp16 partials -> fp16 Sh (tile + transpose).
// grid (16 subtiles, 6 pairs, 16 batch)
// ---------------------------------------------------------------------------
__global__ void __launch_bounds__(256) k_Sreduce() {
    __shared__ float t[32][33];
    const int pxl[6] = {0,0,0,1,1,2}, pyl[6] = {0,1,2,1,2,2};
    const int sub = blockIdx.x, pair = blockIdx.y, bz = blockIdx.z;
    const int px = pxl[pair], py = pyl[pair];
    const int si = sub >> 2, sj = sub & 3;
    const int cc = threadIdx.x & 31, rb = threadIdx.x >> 5;

    const size_t stride = (size_t)Bb * 6 * 16384;
    const __half* p0 = g_Sp + ((size_t)bz * 6 + pair) * 16384;
    const __half* p1 = p0 + stride;
    const __half* p2 = p0 + 2 * stride;
    const size_t gb = (size_t)bz * Cc * Cc;

#pragma unroll
    for (int r = 0; r < 4; r++) {
        int rr = rb + r * 8;
        int li = (si * 32 + rr) * 128 + sj * 32 + cc;
        float s = __half2float(p0[li]) + __half2float(p1[li]) + __half2float(p2[li]);
        t[rr][cc] = s;
        size_t o = gb + (size_t)(px * 128 + si * 32 + rr) * Cc + py * 128 + sj * 32 + cc;
        g_Sh[o] = __float2half_rn(s);
    }
    if (px == py) return;
    __syncthreads();
#pragma unroll
    for (int r = 0; r < 4; r++) {
        int rr = rb + r * 8;
        float s = t[cc][rr];
        size_t o = gb + (size_t)(py * 128 + sj * 32 + rr) * Cc + px * 128 + si * 32 + cc;
        g_Sh[o] = __float2half_rn(s);
    }
}

// ---------------------------------------------------------------------------
// U GEMM (fused U1+U2), 1-pass, cp.async 3-stage, fp16 W. grid (6,3,16).
// ---------------------------------------------------------------------------
__global__ void __launch_bounds__(256) gemm_U() {
    extern __shared__ char dsm[];
    const int tid = threadIdx.x, lane = tid & 31, wid = tid >> 5;
    const int wm = wid & 3, wn = wid >> 2;
    const int sel = blockIdx.x >= 3;
    const int bx = blockIdx.x - (sel ? 3 : 0);
    const int by = blockIdx.y, bz = blockIdx.z;
    const uint32_t smb = smem_u32(dsm);

    const __half* Ax = (sel ? g_W2h : g_W1h) + (size_t)bx * 128 * Cc;
    const __half* Bx = g_Sh + (size_t)bz * Cc * Cc + (size_t)by * 128 * Cc;
    float* Cf = sel ? g_U2 : g_U1;

    int rw[2], qq[2];
#pragma unroll
    for (int j = 0; j < 2; j++) { int u = tid + 256 * j; rw[j] = u >> 2; qq[j] = u & 3; }

    float acc[2][8][4];
#pragma unroll
    for (int i = 0; i < 2; i++)
#pragma unroll
        for (int j = 0; j < 8; j++)
#pragma unroll
            for (int q = 0; q < 4; q++) acc[i][j][q] = 0.f;

#define ISSUE_U(chunk, stage) do { \
    uint32_t _b = smb + (stage) * STAGE_S1; \
    int _k = (chunk) * 32; \
    _Pragma("unroll") \
    for (int _j = 0; _j < 2; _j++) { \
        CP_ASYNC16(_b + rw[_j] * SROW80 + qq[_j] * 16, \
                   Ax + (size_t)rw[_j] * Cc + _k + qq[_j] * 8); \
        CP_ASYNC16(_b + ATILE + rw[_j] * SROW80 + qq[_j] * 16, \
                   Bx + (size_t)rw[_j] * Cc + _k + qq[_j] * 8); \
    } } while (0)

    ISSUE_U(0, 0); CP_COMMIT();
    ISSUE_U(1, 1); CP_COMMIT();

    const int nch = Cc / 32;   // 12
    int st = 0;
    for (int i = 0; i < nch; i++) {
        if (i == nch - 1) CP_WAIT0(); else CP_WAIT1();
        __syncthreads();
        if (i + 2 < nch) {
            int s2 = st + 2; if (s2 >= 3) s2 -= 3;
            ISSUE_U(i + 2, s2); CP_COMMIT();
        }
        compute_nt1(smb + st * STAGE_S1, wm, wn, lane, acc);
        if (++st == 3) st = 0;
    }
#undef ISSUE_U

    float* sC = (float*)dsm;
#pragma unroll
    for (int hp = 0; hp < 2; hp++) {
        __syncthreads();
        if ((wm >> 1) == hp) {
            const int lrow = (wm & 1) * 32;
#pragma unroll
            for (int ti = 0; ti < 2; ti++)
#pragma unroll
                for (int j = 0; j < 8; j++) {
                    int row0 = lrow + ti * 16 + (lane >> 2);
                    int col  = wn * 64 + j * 8 + (lane & 3) * 2;
                    *(float2*)(sC + row0 * 132 + col)       = make_float2(acc[ti][j][0], acc[ti][j][1]);
                    *(float2*)(sC + (row0 + 8) * 132 + col) = make_float2(acc[ti][j][2], acc[ti][j][3]);
                }
        }
        __syncthreads();
        const int row = tid >> 2, quad = tid & 3;
        const float* src = sC + row * 132 + quad * 32;
        size_t base = ((size_t)bz * Cc + bx * 128 + hp * 64 + row) * Cc + by * 128 + quad * 32;
#pragma unroll
        for (int j = 0; j < 32; j += 4)
            *(float4*)(Cf + base + j) = *(const float4*)(src + j);
    }
}

// ---------------------------------------------------------------------------
// out GEMM, 1-pass, BK=32, cp.async 3-stage, 2 blocks/SM:
// out = Mh Xh + mb. Epilogue in two 64-row passes. grid (3,32,16).
// ---------------------------------------------------------------------------
__global__ void __launch_bounds__(256) gemm_out(float* __restrict__ out)
{
    extern __shared__ char dsm[];
    const int tid = threadIdx.x, lane = tid & 31, wid = tid >> 5;
    const int wm = wid & 3, wn = wid >> 2;
    const int bx = blockIdx.x, by = blockIdx.y, bz = blockIdx.z;
    const uint32_t smb = smem_u32(dsm);

    const __half* pA = g_Mh + (size_t)bz * Cc * Cc + (size_t)bx * 128 * Cc;
    const __half* pB = g_Xh + (size_t)bz * Cc * Nn + by * 128;

    int arw[2], aq[2];
#pragma unroll
    for (int j = 0; j < 2; j++) { int u = tid + 256 * j; arw[j] = u >> 2; aq[j] = u & 3; }
    int brw[2], bq[2];
#pragma unroll
    for (int j = 0; j < 2; j++) { int u = tid + 256 * j; brw[j] = u >> 4; bq[j] = u & 15; }

    float acc[2][8][4];
#pragma unroll
    for (int i = 0; i < 2; i++)
#pragma unroll
        for (int j = 0; j < 8; j++)
#pragma unroll
            for (int q = 0; q < 4; q++) acc[i][j][q] = 0.f;

#define ISSUE_O(chunk, stage) do { \
    uint32_t _b = smb + (stage) * STAGE_O32; \
    int _k = (chunk) * 32; \
    _Pragma("unroll") \
    for (int _j = 0; _j < 2; _j++) { \
        CP_ASYNC16(_b + arw[_j] * SROW80 + aq[_j] * 16, \
                   pA + (size_t)arw[_j] * Cc + _k + aq[_j] * 8); \
        CP_ASYNC16(_b + ATILE + brw[_j] * BPITCH + bq[_j] * 16, \
                   pB + (size_t)(_k + brw[_j]) * Nn + bq[_j] * 8); \
    } } while (0)

    ISSUE_O(0, 0); CP_COMMIT();
    ISSUE_O(1, 1); CP_COMMIT();

    const int nch = Cc / 32;   // 12
    int st = 0;
    for (int i = 0; i < nch; i++) {
        if (i == nch - 1) CP_WAIT0(); else CP_WAIT1();
        __syncthreads();
        if (i + 2 < nch) {
            int s2 = st + 2; if (s2 >= 3) s2 -= 3;
            ISSUE_O(i + 2, s2); CP_COMMIT();
        }
        uint32_t sb = smb + st * STAGE_O32;
        compute_o32(sb, sb + ATILE, wm, wn, lane, acc);
        if (++st == 3) st = 0;
    }
#undef ISSUE_O

    float* sC = (float*)dsm;
#pragma unroll
    for (int hp = 0; hp < 2; hp++) {
        __syncthreads();
        if ((wm >> 1) == hp) {
            const int lrow = (wm & 1) * 32;
#pragma unroll
            for (int ti = 0; ti < 2; ti++)
#pragma unroll
                for (int j = 0; j < 8; j++) {
                    int row0 = lrow + ti * 16 + (lane >> 2);
                    int col  = wn * 64 + j * 8 + (lane & 3) * 2;
                    *(float2*)(sC + row0 * 132 + col)       = make_float2(acc[ti][j][0], acc[ti][j][1]);
                    *(float2*)(sC + (row0 + 8) * 132 + col) = make_float2(acc[ti][j][2], acc[ti][j][3]);
                }
        }
        __syncthreads();
        const int row = tid >> 2, quad = tid & 3;
        const float* src = sC + row * 132 + quad * 32;
        const int grow = bx * 128 + hp * 64 + row;
        float bias = g_mb[bz * Cc + grow];
        float* dst = out + ((size_t)bz * Cc + grow) * (size_t)Nn + by * 128 + quad * 32;
#pragma unroll
        for (int j = 0; j < 32; j += 4) {
            float4 v4 = *(const float4*)(src + j);
            *(float4*)(dst + j) = make_float4(v4.x + bias, v4.y + bias,
                                              v4.z + bias, v4.w + bias);
        }
    }
}

// ---------------------------------------------------------------------------
// k_attn1: split-K (3 x 128-wide) partial Gqk + row reductions.
// grid (3, HEADS, Bb).
// ---------------------------------------------------------------------------
__global__ void __launch_bounds__(256) k_attn1(
    const float* __restrict__ w1, const float* __restrict__ w2)
{
    extern __shared__ float satt[];
    float* sU = satt;
    float* sW = satt + CH * 130;

    const int kt = blockIdx.x, h = blockIdx.y, b = blockIdx.z;
    const int k0 = kt * 128;
    const int tid = threadIdx.x;
    const int warp = tid >> 5, lane = tid & 31;

    const float* U1  = &g_U1[(size_t)b * Cc * Cc + (size_t)h * CH * Cc];
    const float* U2  = &g_U2[(size_t)b * Cc * Cc + (size_t)h * CH * Cc];
    const float* w1h = w1 + (size_t)h * CH * Cc;
    const float* w2h = w2 + (size_t)h * CH * Cc;

    for (int i = tid; i < CH * 128; i += 256) {
        int c = i >> 7, kk = i & 127;
        sU[c * 130 + kk] = U1[c * Cc + k0 + kk];
        sW[c * 130 + kk] = w2h[c * Cc + k0 + kk];
    }
    __syncthreads();

    const int ci0 = (tid >> 4) * 3, di0 = (tid & 15) * 3;
    float acc[3][3];
#pragma unroll
    for (int i = 0; i < 3; i++)
#pragma unroll
        for (int j = 0; j < 3; j++) acc[i][j] = 0.f;
#pragma unroll 8
    for (int kk = 0; kk < 128; kk++) {
        float u[3], w[3];
#pragma unroll
        for (int i = 0; i < 3; i++) u[i] = sU[(ci0 + i) * 130 + kk];
#pragma unroll
        for (int j = 0; j < 3; j++) w[j] = sW[(di0 + j) * 130 + kk];
#pragma unroll
        for (int i = 0; i < 3; i++)
#pragma unroll
            for (int j = 0; j < 3; j++) acc[i][j] += u[i] * w[j];
    }
    float* Gp = g_Gp + (((size_t)kt * Bb + b) * HEADS + h) * (CH * CH);
#pragma unroll
    for (int i = 0; i < 3; i++)
#pragma unroll
        for (int j = 0; j < 3; j++)
            Gp[(ci0 + i) * CH + di0 + j] = acc[i][j];

    float* rp = g_rp + (((size_t)kt * Bb + b) * HEADS + h) * (4 * CH);
    for (int c = warp * 6; c < warp * 6 + 6; c++) {
        float aq = 0.f, ak = 0.f, p1 = 0.f, p2 = 0.f;
#pragma unroll
        for (int it = 0; it < 4; it++) {
            int k = k0 + lane + it * 32;
            float w1v = w1h[c * Cc + k];
            float w2v = w2h[c * Cc + k];
            aq += U1[c * Cc + k] * w1v;
            ak += U2[c * Cc + k] * w2v;
            float sv = g_sx[(size_t)b * Cc + k];
            p1 += w1v * sv;
            p2 += w2v * sv;
        }
#pragma unroll
        for (int o = 16; o; o >>= 1) {
            aq += __shfl_xor_sync(0xffffffffu, aq, o);
            ak += __shfl_xor_sync(0xffffffffu, ak, o);
            p1 += __shfl_xor_sync(0xffffffffu, p1, o);
            p2 += __shfl_xor_sync(0xffffffffu, p2, o);
        }
        if (lane == 0) {
            rp[0 * CH + c] = aq;
            rp[1 * CH + c] = ak;
            rp[2 * CH + c] = p1;
            rp[3 * CH + c] = p2;
        }
    }
}

// ---------------------------------------------------------------------------
// k_foldM: combine partials -> softmax A (redundant per kt), fold M k-slice,
// kt==0 writes mb. grid (3, HEADS, Bb).
// ---------------------------------------------------------------------------
__global__ void __launch_bounds__(256) k_foldM(
    const float* __restrict__ w3, const float* __restrict__ b1,
    const float* __restrict__ b2, const float* __restrict__ b3,
    const float* __restrict__ temp)
{
    __shared__ float sAa[CH * 49];
    __shared__ float sW[CH * 130];
    __shared__ float sNq[CH], sNk[CH], sP1[CH], sP2[CH];
    __shared__ float sB1[CH], sB2[CH], sB3[CH];

    const int kt = blockIdx.x, h = blockIdx.y, b = blockIdx.z;
    const int k0 = kt * 128;
    const int tid = threadIdx.x;
    const int warp = tid >> 5, lane = tid & 31;

    const size_t gstr = (size_t)Bb * HEADS * CH * CH;
    const size_t rstr = (size_t)Bb * HEADS * 4 * CH;
    const float* Gp = g_Gp + ((size_t)b * HEADS + h) * (CH * CH);
    const float* rp = g_rp + ((size_t)b * HEADS + h) * (4 * CH);
    const float* w3h = w3 + (size_t)h * CH * Cc;

    if (tid < CH) {
        sB1[tid] = b1[h * CH + tid];
        sB2[tid] = b2[h * CH + tid];
        sB3[tid] = b3[h * CH + tid];
        sNq[tid] = rp[0 * CH + tid] + rp[rstr + 0 * CH + tid] + rp[2 * rstr + 0 * CH + tid];
        sNk[tid] = rp[1 * CH + tid] + rp[rstr + 1 * CH + tid] + rp[2 * rstr + 1 * CH + tid];
        sP1[tid] = rp[2 * CH + tid] + rp[rstr + 2 * CH + tid] + rp[2 * rstr + 2 * CH + tid];
        sP2[tid] = rp[3 * CH + tid] + rp[rstr + 3 * CH + tid] + rp[2 * rstr + 3 * CH + tid];
    }
    for (int i = tid; i < CH * 128; i += 256) {
        int d = i >> 7, kk = i & 127;
        sW[d * 130 + kk] = w3h[d * Cc + k0 + kk];
    }
    __syncthreads();

    const float tH = temp[h];
#pragma unroll
    for (int e = 0; e < 9; e++) {
        int idx = tid + 256 * e;
        int c = idx / CH, d = idx - c * CH;
        float g = Gp[idx] + Gp[gstr + idx] + Gp[2 * gstr + idx];
        float b1c = sB1[c], b2d = sB2[d];
        float nq = sqrtf(fmaxf(sNq[c] + 2.f * b1c * sP1[c] + 4096.f * b1c * b1c, 0.f));
        float nk = sqrtf(fmaxf(sNk[d] + 2.f * b2d * sP2[d] + 4096.f * b2d * b2d, 0.f));
        g = g + b1c * sP2[d] + b2d * sP1[c] + 4096.f * b1c * b2d;
        sAa[c * 49 + d] = g / (fmaxf(nq, 1e-12f) * fmaxf(nk, 1e-12f)) * tH;
    }
    __syncthreads();

    for (int c = warp * 6; c < warp * 6 + 6; c++) {
        float a0 = sAa[c * 49 + lane];
        float a1 = (lane < 16) ? sAa[c * 49 + 32 + lane] : -3.402823466e38f;
        float m = fmaxf(a0, a1);
#pragma unroll
        for (int o = 16; o; o >>= 1) m = fmaxf(m, __shfl_xor_sync(0xffffffffu, m, o));
        float e0 = __expf(a0 - m);
        float e1 = (lane < 16) ? __expf(a1 - m) : 0.f;
        float s = e0 + e1;
#pragma unroll
        for (int o = 16; o; o >>= 1) s += __shfl_xor_sync(0xffffffffu, s, o);
        float inv = 1.f / s;
        sAa[c * 49 + lane] = e0 * inv;
        if (lane < 16) sAa[c * 49 + 32 + lane] = e1 * inv;
    }
    __syncthreads();

    if (kt == 0 && tid < CH) {
        float s = sB3[tid];
#pragma unroll 8
        for (int d = 0; d < CH; d++) s += sAa[tid * 49 + d] * sB3[d];
        g_mb[b * Cc + h * CH + tid] = s;
    }

    const int kkl = tid & 127, half = tid >> 7;
    float w[CH];
#pragma unroll 12
    for (int d = 0; d < CH; d++) w[d] = sW[d * 130 + kkl];

    __half* Mrow = g_Mh + (size_t)b * Cc * Cc + (size_t)(h * CH) * Cc + k0 + kkl;
    for (int c = half * 24; c < half * 24 + 24; c++) {
        float s = w[0] * sAa[c * 49 + 0] + sW[c * 130 + kkl];
#pragma unroll 12
        for (int d = 1; d < CH; d++) s += sAa[c * 49 + d] * w[d];
        if (h * CH + c == k0 + kkl) s += 1.f;
        Mrow[(size_t)c * Cc] = __float2half_rn(s);
    }
}

// ---------------------------------------------------------------------------
extern "C" void kernel_launch(void* const* d_in, const int* in_sizes, int n_in,
                              void* d_out, int out_size)
{
    (void)in_sizes; (void)n_in; (void)out_size;
    const float* x    = (const float*)d_in[0];
    const float* w1   = (const float*)d_in[1];
    const float* b1   = (const float*)d_in[2];
    const float* w2   = (const float*)d_in[3];
    const float* b2   = (const float*)d_in[4];
    const float* w3   = (const float*)d_in[5];
    const float* b3   = (const float*)d_in[6];
    const float* temp = (const float*)d_in[7];
    float* out = (float*)d_out;

    cudaFuncSetAttribute(gemm_S,   cudaFuncAttributeMaxDynamicSharedMemorySize, DSMEM_S);
    cudaFuncSetAttribute(gemm_U,   cudaFuncAttributeMaxDynamicSharedMemorySize, DSMEM_S);
    cudaFuncSetAttribute(gemm_out, cudaFuncAttributeMaxDynamicSharedMemorySize, DSMEM_O);
    cudaFuncSetAttribute(k_attn1,  cudaFuncAttributeMaxDynamicSharedMemorySize, ATTN1_SM);

    k_convert<<<Bb * Cc, 256>>>(x);
    k_convW<<<dim3(WSZ / 1024, 2), 256>>>(w1, w2);

    gemm_S<<<dim3(6, 3, Bb), 256, DSMEM_S>>>();
    k_Sreduce<<<dim3(16, 6, Bb), 256>>>();

    gemm_U<<<dim3(6, 3, Bb), 256, DSMEM_S>>>();

    k_attn1<<<dim3(3, HEADS, Bb), 256, ATTN1_SM>>>(w1, w2);
    k_foldM<<<dim3(3, HEADS, Bb), 256>>>(w3, b1, b2, b3, temp);

    gemm_out<<<dim3(3, 32, Bb), 256, DSMEM_O>>>(out);
}